// round 3
// baseline (speedup 1.0000x reference)
#include <cuda_runtime.h>
#include <math.h>

#define N_NODES 20000
#define N_EDGES 240000
#define N_GRAPHS 200
#define D_IN 118
#define HDIM 256
#define NB 10
#define RH 100
#define NLAYER 3
#define SH9 9
#define KTP (SH9*HDIM)   // 2304

// ---------------- static device scratch (no allocation allowed) ----------------
__device__ float g_hA[N_NODES*HDIM];
__device__ float g_hB[N_NODES*HDIM];
__device__ float g_agg[N_NODES*HDIM];
__device__ float g_G[(size_t)N_NODES*KTP];          // 184 MB
__device__ float g_radial[(size_t)N_EDGES*HDIM];    // 245 MB
__device__ float g_act[(size_t)N_EDGES*RH];         // 96 MB
__device__ float g_sh[N_EDGES*SH9];
__device__ float g_emb[N_EDGES*NB];
__device__ int   g_deg[N_NODES];
__device__ int   g_rowptr[N_NODES+1];
__device__ int   g_cursor[N_NODES];
__device__ int   g_csr[N_EDGES];
__device__ float g_sums[N_GRAPHS];
__device__ float g_cnts[N_GRAPHS];

// ---------------- small utility kernels ----------------
__global__ void zero_kernel() {
    int i = blockIdx.x*blockDim.x + threadIdx.x;
    if (i < N_NODES) g_deg[i] = 0;
    if (i < N_GRAPHS) { g_sums[i] = 0.0f; g_cnts[i] = 0.0f; }
}

__global__ void hist_kernel(const int* __restrict__ dst, const int* __restrict__ batch) {
    int i = blockIdx.x*blockDim.x + threadIdx.x;
    if (i < N_EDGES) atomicAdd(&g_deg[dst[i]], 1);
    if (i < N_NODES) atomicAdd(&g_cnts[batch[i]], 1.0f);
}

// single-block exclusive scan over deg -> rowptr, cursor
__global__ void scan_kernel() {
    __shared__ int s[1024];
    __shared__ int carry;
    int tid = threadIdx.x;
    if (tid == 0) carry = 0;
    __syncthreads();
    for (int base = 0; base < N_NODES; base += 1024) {
        int i = base + tid;
        int v = (i < N_NODES) ? g_deg[i] : 0;
        s[tid] = v;
        __syncthreads();
        for (int off = 1; off < 1024; off <<= 1) {
            int t = (tid >= off) ? s[tid-off] : 0;
            __syncthreads();
            if (tid >= off) s[tid] += t;
            __syncthreads();
        }
        int inc = s[tid] + carry;
        if (i < N_NODES) { g_rowptr[i+1] = inc; g_cursor[i] = inc - v; }
        if (i == 0) g_rowptr[0] = 0;
        __syncthreads();
        if (tid == 1023) carry = inc;
        __syncthreads();
    }
}

__global__ void build_csr_kernel(const int* __restrict__ dst) {
    int e = blockIdx.x*blockDim.x + threadIdx.x;
    if (e >= N_EDGES) return;
    int p = atomicAdd(&g_cursor[dst[e]], 1);
    g_csr[p] = e;
}

// per-edge geometry: spherical harmonics (l<=2) and cosine radial basis
__global__ void edge_geom_kernel(const float* __restrict__ pos,
                                 const float* __restrict__ shift,
                                 const float* __restrict__ lattice,
                                 const int* __restrict__ batch,
                                 const int* __restrict__ src,
                                 const int* __restrict__ dst) {
    int e = blockIdx.x*blockDim.x + threadIdx.x;
    if (e >= N_EDGES) return;
    int s = src[e], d = dst[e];
    int b = batch[s];
    float sx = shift[e*3+0], sy = shift[e*3+1], sz = shift[e*3+2];
    const float* L = lattice + b*9;
    float v[3];
    #pragma unroll
    for (int j = 0; j < 3; j++)
        v[j] = pos[d*3+j] - pos[s*3+j] + sx*L[j] + sy*L[3+j] + sz*L[6+j];
    float len = sqrtf(v[0]*v[0] + v[1]*v[1] + v[2]*v[2]);
    float inv = 1.0f/(len + 1e-12f);
    float ux = v[0]*inv, uy = v[1]*inv, uz = v[2]*inv;
    const float c1 = 1.7320508075688772f;   // sqrt(3)
    const float c2 = 3.872983346207417f;    // sqrt(15)
    float* shp = g_sh + e*SH9;
    shp[0] = 1.0f;
    shp[1] = c1*ux;
    shp[2] = c1*uy;
    shp[3] = c1*uz;
    shp[4] = c2*ux*uy;
    shp[5] = c2*uy*uz;
    shp[6] = 1.118033988749895f*(3.0f*uz*uz - 1.0f);   // sqrt(5)/2
    shp[7] = c2*ux*uz;
    shp[8] = 1.9364916731037085f*(ux*ux - uy*uy);      // sqrt(15)/2
    const float step = 5.0f/11.0f;
    const float sq10 = 3.1622776601683795f;
    float* ep = g_emb + e*NB;
    #pragma unroll
    for (int i = 0; i < NB; i++) {
        float val = step*(float)(i+1);
        float diff = (len - val)/step;
        float em = 0.0f;
        if (diff > -1.0f && diff < 1.0f)
            em = cosf(1.5707963267948966f*diff)*sq10;
        ep[i] = em;
    }
}

// act = silu(emb @ r1 + b1): one warp per edge
__global__ void act_kernel(const float* __restrict__ r1, const float* __restrict__ b1) {
    int w = (blockIdx.x*blockDim.x + threadIdx.x) >> 5;
    int lane = threadIdx.x & 31;
    if (w >= N_EDGES) return;
    float em[NB];
    const float* ep = g_emb + w*NB;
    #pragma unroll
    for (int i = 0; i < NB; i++) em[i] = ep[i];
    for (int j = lane; j < RH; j += 32) {
        float s = b1[j];
        #pragma unroll
        for (int i = 0; i < NB; i++) s += em[i]*r1[i*RH + j];
        g_act[(size_t)w*RH + j] = s/(1.0f + expf(-s));  // silu
    }
}

// scatter: G[n, a, k] = sum_{e: dst=n} sh[e,a] * h[src[e],k] * radial[e,k]
// one warp per node; lane handles k = lane + 32*kk, kk<8; 9x8 accumulators
__global__ void __launch_bounds__(256) scatter_kernel(const float* __restrict__ h,
                                                      const int* __restrict__ src) {
    int n = blockIdx.x*8 + (threadIdx.x >> 5);
    int lane = threadIdx.x & 31;
    if (n >= N_NODES) return;
    float acc[SH9][8];
    #pragma unroll
    for (int a = 0; a < SH9; a++)
        #pragma unroll
        for (int k = 0; k < 8; k++) acc[a][k] = 0.0f;
    int beg = g_rowptr[n], end = g_rowptr[n+1];
    for (int idx = beg; idx < end; ++idx) {
        int e = g_csr[idx];
        int s = src[e];
        float shv[SH9];
        const float* sp = g_sh + e*SH9;
        #pragma unroll
        for (int a = 0; a < SH9; a++) shv[a] = sp[a];
        const float* hp = h + (size_t)s*HDIM + lane;
        const float* rp = g_radial + (size_t)e*HDIM + lane;
        #pragma unroll
        for (int k = 0; k < 8; k++) {
            float hs = hp[k*32]*rp[k*32];
            #pragma unroll
            for (int a = 0; a < SH9; a++) acc[a][k] += shv[a]*hs;
        }
    }
    float* gp = g_G + (size_t)n*KTP + lane;
    #pragma unroll
    for (int a = 0; a < SH9; a++)
        #pragma unroll
        for (int k = 0; k < 8; k++)
            gp[a*HDIM + k*32] = acc[a][k];
}

// ---------------- SGEMM: C = act(alpha * A[M,K] @ B[K,N] (+ C)) ----------------
// 128x128 block tile, BK=16, 8x8 per-thread microtile, 256 threads.
// ACT: 0 = none, 1 = gelu(tanh approx).  LOADC: accumulate onto existing C.
template<int ACT, int LOADC>
__global__ void __launch_bounds__(256) sgemm_kernel(int M, int N, int K,
    const float* __restrict__ A, const float* __restrict__ B,
    float* __restrict__ C, float alpha)
{
    constexpr int BM = 128, BN = 128, BK = 16;
    __shared__ float As[BK][BM+4];
    __shared__ float Bs[BK][BN];
    int bm = blockIdx.y*BM, bn = blockIdx.x*BN;
    int tid = threadIdx.x;
    int tx = tid & 15, ty = tid >> 4;
    float acc[8][8];
    #pragma unroll
    for (int i = 0; i < 8; i++)
        #pragma unroll
        for (int j = 0; j < 8; j++) acc[i][j] = 0.0f;
    int arow = tid >> 1;
    int acol = (tid & 1)*8;
    int brow = tid >> 7;          // 0 or 1
    int bcol = tid & 127;
    bool minterior = (bm + BM <= M);
    for (int k0 = 0; k0 < K; k0 += BK) {
        bool kfull = (k0 + BK <= K);
        if (minterior && kfull) {
            const float* Ap = A + (size_t)(bm+arow)*K + k0 + acol;
            #pragma unroll
            for (int j = 0; j < 8; j++) As[acol+j][arow] = Ap[j];
        } else {
            int gm = bm + arow;
            #pragma unroll
            for (int j = 0; j < 8; j++) {
                int gk = k0 + acol + j;
                As[acol+j][arow] = (gm < M && gk < K) ? A[(size_t)gm*K + gk] : 0.0f;
            }
        }
        if (kfull) {
            #pragma unroll
            for (int i = 0; i < 8; i++)
                Bs[i*2+brow][bcol] = B[(size_t)(k0+i*2+brow)*N + bn + bcol];
        } else {
            #pragma unroll
            for (int i = 0; i < 8; i++) {
                int gk = k0 + i*2 + brow;
                Bs[i*2+brow][bcol] = (gk < K) ? B[(size_t)gk*N + bn + bcol] : 0.0f;
            }
        }
        __syncthreads();
        #pragma unroll
        for (int kk = 0; kk < BK; kk++) {
            float4 a0 = *reinterpret_cast<const float4*>(&As[kk][ty*8]);
            float4 a1 = *reinterpret_cast<const float4*>(&As[kk][ty*8+4]);
            float4 b0 = *reinterpret_cast<const float4*>(&Bs[kk][tx*8]);
            float4 b1 = *reinterpret_cast<const float4*>(&Bs[kk][tx*8+4]);
            float a[8] = {a0.x,a0.y,a0.z,a0.w,a1.x,a1.y,a1.z,a1.w};
            float b[8] = {b0.x,b0.y,b0.z,b0.w,b1.x,b1.y,b1.z,b1.w};
            #pragma unroll
            for (int i = 0; i < 8; i++)
                #pragma unroll
                for (int j = 0; j < 8; j++)
                    acc[i][j] += a[i]*b[j];
        }
        __syncthreads();
    }
    #pragma unroll
    for (int i = 0; i < 8; i++) {
        int gm = bm + ty*8 + i;
        if (gm < M) {
            float* crow = C + (size_t)gm*N + bn + tx*8;
            #pragma unroll
            for (int j = 0; j < 8; j++) {
                float v = alpha*acc[i][j];
                if (LOADC) v += crow[j];
                if (ACT == 1) {
                    float x = v;
                    float inner = 0.7978845608028654f*(x + 0.044715f*x*x*x);
                    v = 0.5f*x*(1.0f + tanhf(inner));
                }
                crow[j] = v;
            }
        }
    }
}

// readout: node_out = h @ Wout, segment-sum by graph
__global__ void readout_kernel(const float* __restrict__ h,
                               const float* __restrict__ Wout,
                               const int* __restrict__ batch) {
    int n = blockIdx.x*8 + (threadIdx.x >> 5);
    int lane = threadIdx.x & 31;
    if (n >= N_NODES) return;
    float s = 0.0f;
    #pragma unroll
    for (int k = 0; k < 8; k++)
        s += h[(size_t)n*HDIM + k*32 + lane]*Wout[k*32 + lane];
    #pragma unroll
    for (int o = 16; o > 0; o >>= 1) s += __shfl_xor_sync(0xffffffffu, s, o);
    if (lane == 0) atomicAdd(&g_sums[batch[n]], s);
}

__global__ void finalize_kernel(float* __restrict__ out) {
    int g = threadIdx.x;
    if (g < N_GRAPHS) out[g] = g_sums[g]/fmaxf(g_cnts[g], 1.0f);
}

// ---------------- launch ----------------
extern "C" void kernel_launch(void* const* d_in, const int* in_sizes, int n_in,
                              void* d_out, int out_size) {
    (void)in_sizes; (void)n_in; (void)out_size;
    const float* x       = (const float*)d_in[0];
    const float* pos     = (const float*)d_in[1];
    const float* shift   = (const float*)d_in[2];
    const float* lattice = (const float*)d_in[3];
    const float* W_embed = (const float*)d_in[4];
    const float* r1      = (const float*)d_in[5];
    const float* b1      = (const float*)d_in[6];
    const float* r2      = (const float*)d_in[7];
    const float* Wtp     = (const float*)d_in[8];
    const float* Wself   = (const float*)d_in[9];
    const float* Wskip   = (const float*)d_in[10];
    const float* Wout    = (const float*)d_in[11];
    const int*   eidx    = (const int*)d_in[12];
    const int*   batch   = (const int*)d_in[13];
    const int* esrc = eidx;
    const int* edst = eidx + N_EDGES;
    float* out = (float*)d_out;

    float *hA, *hB, *agg, *G, *radial, *act;
    cudaGetSymbolAddress((void**)&hA,     g_hA);
    cudaGetSymbolAddress((void**)&hB,     g_hB);
    cudaGetSymbolAddress((void**)&agg,    g_agg);
    cudaGetSymbolAddress((void**)&G,      g_G);
    cudaGetSymbolAddress((void**)&radial, g_radial);
    cudaGetSymbolAddress((void**)&act,    g_act);

    const int TB = 256;
    zero_kernel<<<(N_NODES + TB - 1)/TB, TB>>>();
    hist_kernel<<<(N_EDGES + TB - 1)/TB, TB>>>(edst, batch);
    scan_kernel<<<1, 1024>>>();
    build_csr_kernel<<<(N_EDGES + TB - 1)/TB, TB>>>(edst);
    edge_geom_kernel<<<(N_EDGES + TB - 1)/TB, TB>>>(pos, shift, lattice, batch, esrc, edst);

    dim3 gNode(HDIM/128, (N_NODES + 127)/128);   // (2, 157)
    dim3 gEdge(HDIM/128, N_EDGES/128);           // (2, 1875)

    // h = x @ W_embed
    sgemm_kernel<0,0><<<gNode, 256>>>(N_NODES, HDIM, D_IN, x, W_embed, hA, 1.0f);

    float* hc = hA;
    float* hn = hB;
    const float inv_sqrt_deg = 0.28867513459481287f;  // 1/sqrt(12)

    for (int l = 0; l < NLAYER; l++) {
        // act = silu(emb @ r1[l] + b1[l])
        act_kernel<<<(N_EDGES + 7)/8, 256>>>(r1 + l*NB*RH, b1 + l*RH);
        // radial = act @ r2[l]
        sgemm_kernel<0,0><<<gEdge, 256>>>(N_EDGES, HDIM, RH, act, r2 + l*RH*HDIM, radial, 1.0f);
        // G[n,a,k] = sum_edges sh_a * h[src]*radial
        scatter_kernel<<<(N_NODES + 7)/8, 256>>>(hc, esrc);
        // agg = inv_sqrt_deg * G @ Wtp_flat[l]
        sgemm_kernel<0,0><<<gNode, 256>>>(N_NODES, HDIM, KTP, G,
                                          Wtp + (size_t)l*SH9*HDIM*HDIM, agg, inv_sqrt_deg);
        // h_next = gelu(agg @ Wself[l] + h @ Wskip[l])
        sgemm_kernel<0,0><<<gNode, 256>>>(N_NODES, HDIM, HDIM, agg, Wself + l*HDIM*HDIM, hn, 1.0f);
        sgemm_kernel<1,1><<<gNode, 256>>>(N_NODES, HDIM, HDIM, hc,  Wskip + l*HDIM*HDIM, hn, 1.0f);
        float* t = hc; hc = hn; hn = t;
    }

    readout_kernel<<<(N_NODES + 7)/8, 256>>>(hc, Wout, batch);
    finalize_kernel<<<1, 256>>>(out);
}

// round 4
// speedup vs baseline: 2.0524x; 2.0524x over previous
#include <cuda_runtime.h>
#include <cuda_bf16.h>
#include <math.h>
#include <stdint.h>

#define N_NODES 20000
#define N_EDGES 240000
#define N_GRAPHS 200
#define D_IN 118
#define HDIM 256
#define NB 10
#define RH 100
#define NLAYER 3
#define SH9 9
#define KTP (SH9*HDIM)   // 2304

// ---------------- static device scratch (no allocation allowed) ----------------
__device__ float g_hA[N_NODES*HDIM];
__device__ float g_hB[N_NODES*HDIM];
__device__ float g_agg[N_NODES*HDIM];
__device__ float g_G[(size_t)N_NODES*KTP];          // 184 MB
__device__ float g_radial[(size_t)N_EDGES*HDIM];    // 245 MB
__device__ float g_act[(size_t)N_EDGES*RH];         // 96 MB
__device__ float g_sh[N_EDGES*SH9];
__device__ float g_emb[N_EDGES*NB];
__device__ int   g_deg[N_NODES];
__device__ int   g_rowptr[N_NODES+1];
__device__ int   g_cursor[N_NODES];
__device__ int   g_csr[N_EDGES];
__device__ float g_sums[N_GRAPHS];
__device__ float g_cnts[N_GRAPHS];

// bf16 hi/lo transposed weights: [N][Kpad] per weight matrix
// embed: 256*128 = 32768
// r2[3]: 3 * 256*128 = 98304
// Wtp[3]: 3 * 256*2304 = 1769472
// Wself[3]: 3 * 256*256 = 196608
// Wskip[3]: 3 * 256*256 = 196608
#define OFF_EMB   0
#define OFF_R2    32768
#define OFF_WTP   131072
#define OFF_WSELF 1900544
#define OFF_WSKIP 2097152
#define BT_TOTAL  2293760
__device__ __nv_bfloat16 g_bhi[BT_TOTAL];
__device__ __nv_bfloat16 g_blo[BT_TOTAL];

// ---------------- small utility kernels ----------------
__global__ void zero_kernel() {
    int i = blockIdx.x*blockDim.x + threadIdx.x;
    if (i < N_NODES) g_deg[i] = 0;
    if (i < N_GRAPHS) { g_sums[i] = 0.0f; g_cnts[i] = 0.0f; }
}

__global__ void hist_kernel(const int* __restrict__ dst, const int* __restrict__ batch) {
    int i = blockIdx.x*blockDim.x + threadIdx.x;
    if (i < N_EDGES) atomicAdd(&g_deg[dst[i]], 1);
    if (i < N_NODES) atomicAdd(&g_cnts[batch[i]], 1.0f);
}

// single-block exclusive scan over deg -> rowptr, cursor
__global__ void scan_kernel() {
    __shared__ int s[1024];
    __shared__ int carry;
    int tid = threadIdx.x;
    if (tid == 0) carry = 0;
    __syncthreads();
    for (int base = 0; base < N_NODES; base += 1024) {
        int i = base + tid;
        int v = (i < N_NODES) ? g_deg[i] : 0;
        s[tid] = v;
        __syncthreads();
        for (int off = 1; off < 1024; off <<= 1) {
            int t = (tid >= off) ? s[tid-off] : 0;
            __syncthreads();
            if (tid >= off) s[tid] += t;
            __syncthreads();
        }
        int inc = s[tid] + carry;
        if (i < N_NODES) { g_rowptr[i+1] = inc; g_cursor[i] = inc - v; }
        if (i == 0) g_rowptr[0] = 0;
        __syncthreads();
        if (tid == 1023) carry = inc;
        __syncthreads();
    }
}

__global__ void build_csr_kernel(const int* __restrict__ dst) {
    int e = blockIdx.x*blockDim.x + threadIdx.x;
    if (e >= N_EDGES) return;
    int p = atomicAdd(&g_cursor[dst[e]], 1);
    g_csr[p] = e;
}

// per-edge geometry: spherical harmonics (l<=2) and cosine radial basis
__global__ void edge_geom_kernel(const float* __restrict__ pos,
                                 const float* __restrict__ shift,
                                 const float* __restrict__ lattice,
                                 const int* __restrict__ batch,
                                 const int* __restrict__ src,
                                 const int* __restrict__ dst) {
    int e = blockIdx.x*blockDim.x + threadIdx.x;
    if (e >= N_EDGES) return;
    int s = src[e], d = dst[e];
    int b = batch[s];
    float sx = shift[e*3+0], sy = shift[e*3+1], sz = shift[e*3+2];
    const float* L = lattice + b*9;
    float v[3];
    #pragma unroll
    for (int j = 0; j < 3; j++)
        v[j] = pos[d*3+j] - pos[s*3+j] + sx*L[j] + sy*L[3+j] + sz*L[6+j];
    float len = sqrtf(v[0]*v[0] + v[1]*v[1] + v[2]*v[2]);
    float inv = 1.0f/(len + 1e-12f);
    float ux = v[0]*inv, uy = v[1]*inv, uz = v[2]*inv;
    const float c1 = 1.7320508075688772f;   // sqrt(3)
    const float c2 = 3.872983346207417f;    // sqrt(15)
    float* shp = g_sh + e*SH9;
    shp[0] = 1.0f;
    shp[1] = c1*ux;
    shp[2] = c1*uy;
    shp[3] = c1*uz;
    shp[4] = c2*ux*uy;
    shp[5] = c2*uy*uz;
    shp[6] = 1.118033988749895f*(3.0f*uz*uz - 1.0f);   // sqrt(5)/2
    shp[7] = c2*ux*uz;
    shp[8] = 1.9364916731037085f*(ux*ux - uy*uy);      // sqrt(15)/2
    const float step = 5.0f/11.0f;
    const float sq10 = 3.1622776601683795f;
    float* ep = g_emb + e*NB;
    #pragma unroll
    for (int i = 0; i < NB; i++) {
        float val = step*(float)(i+1);
        float diff = (len - val)/step;
        float em = 0.0f;
        if (diff > -1.0f && diff < 1.0f)
            em = cosf(1.5707963267948966f*diff)*sq10;
        ep[i] = em;
    }
}

// act = silu(emb @ r1 + b1): one warp per edge
__global__ void act_kernel(const float* __restrict__ r1, const float* __restrict__ b1) {
    int w = (blockIdx.x*blockDim.x + threadIdx.x) >> 5;
    int lane = threadIdx.x & 31;
    if (w >= N_EDGES) return;
    float em[NB];
    const float* ep = g_emb + w*NB;
    #pragma unroll
    for (int i = 0; i < NB; i++) em[i] = ep[i];
    for (int j = lane; j < RH; j += 32) {
        float s = b1[j];
        #pragma unroll
        for (int i = 0; i < NB; i++) s += em[i]*r1[i*RH + j];
        g_act[(size_t)w*RH + j] = s/(1.0f + expf(-s));  // silu
    }
}

// scatter: G[n, a, k] = sum_{e: dst=n} sh[e,a] * h[src[e],k] * radial[e,k]
__global__ void __launch_bounds__(256) scatter_kernel(const float* __restrict__ h,
                                                      const int* __restrict__ src) {
    int n = blockIdx.x*8 + (threadIdx.x >> 5);
    int lane = threadIdx.x & 31;
    if (n >= N_NODES) return;
    float acc[SH9][8];
    #pragma unroll
    for (int a = 0; a < SH9; a++)
        #pragma unroll
        for (int k = 0; k < 8; k++) acc[a][k] = 0.0f;
    int beg = g_rowptr[n], end = g_rowptr[n+1];
    for (int idx = beg; idx < end; ++idx) {
        int e = g_csr[idx];
        int s = src[e];
        float shv[SH9];
        const float* sp = g_sh + e*SH9;
        #pragma unroll
        for (int a = 0; a < SH9; a++) shv[a] = sp[a];
        const float* hp = h + (size_t)s*HDIM + lane;
        const float* rp = g_radial + (size_t)e*HDIM + lane;
        #pragma unroll
        for (int k = 0; k < 8; k++) {
            float hs = hp[k*32]*rp[k*32];
            #pragma unroll
            for (int a = 0; a < SH9; a++) acc[a][k] += shv[a]*hs;
        }
    }
    float* gp = g_G + (size_t)n*KTP + lane;
    #pragma unroll
    for (int a = 0; a < SH9; a++)
        #pragma unroll
        for (int k = 0; k < 8; k++)
            gp[a*HDIM + k*32] = acc[a][k];
}

// ---------------- weight convert/transpose: B[K][N] fp32 -> Bt[N][Kpad] bf16 hi/lo ----------------
__global__ void convertB_kernel(const float* __restrict__ B,
                                __nv_bfloat16* __restrict__ hi,
                                __nv_bfloat16* __restrict__ lo,
                                int K, int Kpad, int N) {
    int i = blockIdx.x*blockDim.x + threadIdx.x;
    if (i >= N*Kpad) return;
    int n = i / Kpad, k = i - n*Kpad;
    float v = (k < K) ? B[(size_t)k*N + n] : 0.0f;
    __nv_bfloat16 h = __float2bfloat16_rn(v);
    hi[i] = h;
    lo[i] = __float2bfloat16_rn(v - __bfloat162float(h));
}

// ---------------- split-bf16 tensor-core GEMM ----------------
// C[M,256] = act(alpha * A[M,K] @ B[K,256] (+C)), B pre-converted to Bt[N][Kpad] bf16 hi/lo.
// 128x128x32 tiles, 8 warps (2x4), warp tile 64x32, mma.m16n8k16, 3-term split.
__device__ __forceinline__ void mma16816(float* c, const uint32_t* a, const uint32_t* b) {
    asm volatile(
        "mma.sync.aligned.m16n8k16.row.col.f32.bf16.bf16.f32 "
        "{%0,%1,%2,%3}, {%4,%5,%6,%7}, {%8,%9}, {%0,%1,%2,%3};\n"
        : "+f"(c[0]), "+f"(c[1]), "+f"(c[2]), "+f"(c[3])
        : "r"(a[0]), "r"(a[1]), "r"(a[2]), "r"(a[3]), "r"(b[0]), "r"(b[1]));
}

__device__ __forceinline__ float gelu_f(float x) {
    float inner = 0.7978845608028654f*(x + 0.044715f*x*x*x);
    return 0.5f*x*(1.0f + tanhf(inner));
}

template<int ACT, int LOADC>
__global__ void __launch_bounds__(256, 1) mma_gemm(int M, int K, int Kpad,
    const float* __restrict__ A,
    const __nv_bfloat16* __restrict__ Bth,
    const __nv_bfloat16* __restrict__ Btl,
    float* __restrict__ C, float alpha)
{
    constexpr int N = 256;
    constexpr int LDSB = 40;  // smem row stride in bf16 (80B = 20 words -> conflict-free)
    __shared__ uint16_t As_h[128*LDSB];
    __shared__ uint16_t As_l[128*LDSB];
    __shared__ uint16_t Bs_h[128*LDSB];
    __shared__ uint16_t Bs_l[128*LDSB];

    int tid = threadIdx.x;
    int lane = tid & 31, warp = tid >> 5;
    int wm = (warp >> 2) * 64;
    int wn = (warp & 3) * 32;
    int bm = blockIdx.y * 128;
    int bn = blockIdx.x * 128;

    float acc[4][4][4];
    #pragma unroll
    for (int i = 0; i < 4; i++)
        #pragma unroll
        for (int j = 0; j < 4; j++)
            #pragma unroll
            for (int r = 0; r < 4; r++) acc[i][j][r] = 0.0f;

    const int arow = tid >> 1, acb = (tid & 1) * 16;
    const int gm = bm + arow;
    const bool aok = gm < M;
    const bool kdiv4 = (K & 3) == 0;
    const int brow = tid >> 1, bcb = (tid & 1) * 16;

    float4 av[4];
    uint4 bhv[2], blv[2];

    auto fetchA = [&](int k0) {
        if (aok && kdiv4 && (k0 + acb + 16 <= K)) {
            const float* p = A + (size_t)gm*K + k0 + acb;
            av[0] = *(const float4*)(p);
            av[1] = *(const float4*)(p + 4);
            av[2] = *(const float4*)(p + 8);
            av[3] = *(const float4*)(p + 12);
        } else {
            const float* p = A + (size_t)gm*K;
            #pragma unroll
            for (int i = 0; i < 4; i++) {
                float t[4];
                #pragma unroll
                for (int j = 0; j < 4; j++) {
                    int kk = k0 + acb + i*4 + j;
                    t[j] = (aok && kk < K) ? p[kk] : 0.0f;
                }
                av[i] = make_float4(t[0], t[1], t[2], t[3]);
            }
        }
    };
    auto fetchB = [&](int k0) {
        const __nv_bfloat16* ph = Bth + (size_t)(bn + brow)*Kpad + k0 + bcb;
        const __nv_bfloat16* pl = Btl + (size_t)(bn + brow)*Kpad + k0 + bcb;
        bhv[0] = *(const uint4*)(ph);
        bhv[1] = *(const uint4*)(ph + 8);
        blv[0] = *(const uint4*)(pl);
        blv[1] = *(const uint4*)(pl + 8);
    };
    auto stage = [&]() {
        uint16_t* da = &As_h[arow*LDSB + acb];
        uint16_t* dal = &As_l[arow*LDSB + acb];
        #pragma unroll
        for (int i = 0; i < 4; i++) {
            float4 v = av[i];
            __nv_bfloat162 h01 = __floats2bfloat162_rn(v.x, v.y);
            __nv_bfloat162 h23 = __floats2bfloat162_rn(v.z, v.w);
            __nv_bfloat162 l01 = __floats2bfloat162_rn(v.x - __bfloat162float(h01.x),
                                                       v.y - __bfloat162float(h01.y));
            __nv_bfloat162 l23 = __floats2bfloat162_rn(v.z - __bfloat162float(h23.x),
                                                       v.w - __bfloat162float(h23.y));
            *(uint32_t*)(da + i*4)     = *(uint32_t*)&h01;
            *(uint32_t*)(da + i*4 + 2) = *(uint32_t*)&h23;
            *(uint32_t*)(dal + i*4)     = *(uint32_t*)&l01;
            *(uint32_t*)(dal + i*4 + 2) = *(uint32_t*)&l23;
        }
        uint16_t* db = &Bs_h[brow*LDSB + bcb];
        uint16_t* dbl = &Bs_l[brow*LDSB + bcb];
        *(uint2*)(db)      = make_uint2(bhv[0].x, bhv[0].y);
        *(uint2*)(db + 4)  = make_uint2(bhv[0].z, bhv[0].w);
        *(uint2*)(db + 8)  = make_uint2(bhv[1].x, bhv[1].y);
        *(uint2*)(db + 12) = make_uint2(bhv[1].z, bhv[1].w);
        *(uint2*)(dbl)      = make_uint2(blv[0].x, blv[0].y);
        *(uint2*)(dbl + 4)  = make_uint2(blv[0].z, blv[0].w);
        *(uint2*)(dbl + 8)  = make_uint2(blv[1].x, blv[1].y);
        *(uint2*)(dbl + 12) = make_uint2(blv[1].z, blv[1].w);
    };

    fetchA(0); fetchB(0);
    for (int k0 = 0; k0 < Kpad; k0 += 32) {
        stage();
        __syncthreads();
        if (k0 + 32 < Kpad) { fetchA(k0 + 32); fetchB(k0 + 32); }
        // compute on smem tile
        #pragma unroll
        for (int kt = 0; kt < 2; kt++) {
            int c = kt*16 + 2*(lane & 3);
            int r0 = lane >> 2;
            uint32_t bh[4][2], bl[4][2];
            #pragma unroll
            for (int nt = 0; nt < 4; nt++) {
                const uint16_t* pb  = &Bs_h[(wn + nt*8 + r0)*LDSB + c];
                const uint16_t* pbl = &Bs_l[(wn + nt*8 + r0)*LDSB + c];
                bh[nt][0] = *(const uint32_t*)(pb);
                bh[nt][1] = *(const uint32_t*)(pb + 8);
                bl[nt][0] = *(const uint32_t*)(pbl);
                bl[nt][1] = *(const uint32_t*)(pbl + 8);
            }
            #pragma unroll
            for (int mt = 0; mt < 4; mt++) {
                const uint16_t* pa  = &As_h[(wm + mt*16 + r0)*LDSB + c];
                const uint16_t* pal = &As_l[(wm + mt*16 + r0)*LDSB + c];
                uint32_t ah[4], al[4];
                ah[0] = *(const uint32_t*)(pa);
                ah[1] = *(const uint32_t*)(pa + 8*LDSB);
                ah[2] = *(const uint32_t*)(pa + 8);
                ah[3] = *(const uint32_t*)(pa + 8*LDSB + 8);
                al[0] = *(const uint32_t*)(pal);
                al[1] = *(const uint32_t*)(pal + 8*LDSB);
                al[2] = *(const uint32_t*)(pal + 8);
                al[3] = *(const uint32_t*)(pal + 8*LDSB + 8);
                #pragma unroll
                for (int nt = 0; nt < 4; nt++) {
                    mma16816(acc[mt][nt], ah, bh[nt]);
                    mma16816(acc[mt][nt], ah, bl[nt]);
                    mma16816(acc[mt][nt], al, bh[nt]);
                }
            }
        }
        __syncthreads();
    }

    // epilogue
    #pragma unroll
    for (int mt = 0; mt < 4; mt++) {
        int rbase = bm + wm + mt*16 + (lane >> 2);
        #pragma unroll
        for (int half = 0; half < 2; half++) {
            int rr = rbase + half*8;
            if (rr < M) {
                #pragma unroll
                for (int nt = 0; nt < 4; nt++) {
                    int cc = bn + wn + nt*8 + 2*(lane & 3);
                    float v0 = alpha*acc[mt][nt][half*2 + 0];
                    float v1 = alpha*acc[mt][nt][half*2 + 1];
                    float* cp = C + (size_t)rr*N + cc;
                    if (LOADC) {
                        float2 old = *(const float2*)cp;
                        v0 += old.x; v1 += old.y;
                    }
                    if (ACT) { v0 = gelu_f(v0); v1 = gelu_f(v1); }
                    *(float2*)cp = make_float2(v0, v1);
                }
            }
        }
    }
}

// readout: node_out = h @ Wout, segment-sum by graph
__global__ void readout_kernel(const float* __restrict__ h,
                               const float* __restrict__ Wout,
                               const int* __restrict__ batch) {
    int n = blockIdx.x*8 + (threadIdx.x >> 5);
    int lane = threadIdx.x & 31;
    if (n >= N_NODES) return;
    float s = 0.0f;
    #pragma unroll
    for (int k = 0; k < 8; k++)
        s += h[(size_t)n*HDIM + k*32 + lane]*Wout[k*32 + lane];
    #pragma unroll
    for (int o = 16; o > 0; o >>= 1) s += __shfl_xor_sync(0xffffffffu, s, o);
    if (lane == 0) atomicAdd(&g_sums[batch[n]], s);
}

__global__ void finalize_kernel(float* __restrict__ out) {
    int g = threadIdx.x;
    if (g < N_GRAPHS) out[g] = g_sums[g]/fmaxf(g_cnts[g], 1.0f);
}

// ---------------- launch ----------------
extern "C" void kernel_launch(void* const* d_in, const int* in_sizes, int n_in,
                              void* d_out, int out_size) {
    (void)in_sizes; (void)n_in; (void)out_size;
    const float* x       = (const float*)d_in[0];
    const float* pos     = (const float*)d_in[1];
    const float* shift   = (const float*)d_in[2];
    const float* lattice = (const float*)d_in[3];
    const float* W_embed = (const float*)d_in[4];
    const float* r1      = (const float*)d_in[5];
    const float* b1      = (const float*)d_in[6];
    const float* r2      = (const float*)d_in[7];
    const float* Wtp     = (const float*)d_in[8];
    const float* Wself   = (const float*)d_in[9];
    const float* Wskip   = (const float*)d_in[10];
    const float* Wout    = (const float*)d_in[11];
    const int*   eidx    = (const int*)d_in[12];
    const int*   batch   = (const int*)d_in[13];
    const int* esrc = eidx;
    const int* edst = eidx + N_EDGES;
    float* out = (float*)d_out;

    float *hA, *hB, *agg, *G, *radial, *act;
    __nv_bfloat16 *bhi, *blo;
    cudaGetSymbolAddress((void**)&hA,     g_hA);
    cudaGetSymbolAddress((void**)&hB,     g_hB);
    cudaGetSymbolAddress((void**)&agg,    g_agg);
    cudaGetSymbolAddress((void**)&G,      g_G);
    cudaGetSymbolAddress((void**)&radial, g_radial);
    cudaGetSymbolAddress((void**)&act,    g_act);
    cudaGetSymbolAddress((void**)&bhi,    g_bhi);
    cudaGetSymbolAddress((void**)&blo,    g_blo);

    const int TB = 256;
    zero_kernel<<<(N_NODES + TB - 1)/TB, TB>>>();
    hist_kernel<<<(N_EDGES + TB - 1)/TB, TB>>>(edst, batch);
    scan_kernel<<<1, 1024>>>();
    build_csr_kernel<<<(N_EDGES + TB - 1)/TB, TB>>>(edst);
    edge_geom_kernel<<<(N_EDGES + TB - 1)/TB, TB>>>(pos, shift, lattice, batch, esrc, edst);

    // convert/transpose all weights to bf16 hi/lo [N][Kpad]
    auto cvt = [&](const float* B, int off, int K, int Kpad) {
        int n = HDIM*Kpad;
        convertB_kernel<<<(n + TB - 1)/TB, TB>>>(B, bhi + off, blo + off, K, Kpad, HDIM);
    };
    cvt(W_embed, OFF_EMB, D_IN, 128);
    for (int l = 0; l < NLAYER; l++) {
        cvt(r2 + (size_t)l*RH*HDIM,        OFF_R2    + l*32768,  RH,   128);
        cvt(Wtp + (size_t)l*SH9*HDIM*HDIM, OFF_WTP   + l*589824, KTP,  2304);
        cvt(Wself + (size_t)l*HDIM*HDIM,   OFF_WSELF + l*65536,  HDIM, 256);
        cvt(Wskip + (size_t)l*HDIM*HDIM,   OFF_WSKIP + l*65536,  HDIM, 256);
    }

    dim3 gNode(2, (N_NODES + 127)/128);   // (2, 157)
    dim3 gEdge(2, N_EDGES/128);           // (2, 1875)

    // h = x @ W_embed
    mma_gemm<0,0><<<gNode, 256>>>(N_NODES, D_IN, 128, x, bhi + OFF_EMB, blo + OFF_EMB, hA, 1.0f);

    float* hc = hA;
    float* hn = hB;
    const float inv_sqrt_deg = 0.28867513459481287f;  // 1/sqrt(12)

    for (int l = 0; l < NLAYER; l++) {
        act_kernel<<<(N_EDGES + 7)/8, 256>>>(r1 + l*NB*RH, b1 + l*RH);
        // radial = act @ r2[l]
        mma_gemm<0,0><<<gEdge, 256>>>(N_EDGES, RH, 128, act,
                                      bhi + OFF_R2 + l*32768, blo + OFF_R2 + l*32768,
                                      radial, 1.0f);
        scatter_kernel<<<(N_NODES + 7)/8, 256>>>(hc, esrc);
        // agg = inv_sqrt_deg * G @ Wtp_flat[l]
        mma_gemm<0,0><<<gNode, 256>>>(N_NODES, KTP, 2304, G,
                                      bhi + OFF_WTP + l*589824, blo + OFF_WTP + l*589824,
                                      agg, inv_sqrt_deg);
        // h_next = gelu(agg @ Wself[l] + h @ Wskip[l])
        mma_gemm<0,0><<<gNode, 256>>>(N_NODES, HDIM, 256, agg,
                                      bhi + OFF_WSELF + l*65536, blo + OFF_WSELF + l*65536,
                                      hn, 1.0f);
        mma_gemm<1,1><<<gNode, 256>>>(N_NODES, HDIM, 256, hc,
                                      bhi + OFF_WSKIP + l*65536, blo + OFF_WSKIP + l*65536,
                                      hn, 1.0f);
        float* t = hc; hc = hn; hn = t;
    }

    readout_kernel<<<(N_NODES + 7)/8, 256>>>(hc, Wout, batch);
    finalize_kernel<<<1, 256>>>(out);
}

// round 6
// speedup vs baseline: 2.3948x; 1.1669x over previous
#include <cuda_runtime.h>
#include <cuda_bf16.h>
#include <math.h>
#include <stdint.h>

#define N_NODES 20000
#define N_EDGES 240000
#define N_GRAPHS 200
#define D_IN 118
#define HDIM 256
#define NB 10
#define RH 100
#define NLAYER 3
#define SH9 9
#define KTP (SH9*HDIM)   // 2304

// ---------------- static device scratch (no allocation allowed) ----------------
__device__ float g_hA[N_NODES*HDIM];
__device__ float g_hB[N_NODES*HDIM];
__device__ float g_radial[(size_t)N_EDGES*HDIM];    // 245 MB
__device__ float g_sh[N_EDGES*SH9];
__device__ float g_emb[N_EDGES*NB];
__device__ int   g_deg[N_NODES];
__device__ int   g_rowptr[N_NODES+1];
__device__ int   g_cursor[N_NODES];
__device__ int   g_csr[N_EDGES];
__device__ float g_sums[N_GRAPHS];
__device__ float g_cnts[N_GRAPHS];

// pre-split bf16 A operands
__device__ __nv_bfloat16 g_act_h[(size_t)N_EDGES*128];  // 61 MB
__device__ __nv_bfloat16 g_act_l[(size_t)N_EDGES*128];
__device__ __nv_bfloat16 g_Gh[(size_t)N_NODES*KTP];     // 92 MB
__device__ __nv_bfloat16 g_Gl[(size_t)N_NODES*KTP];
// combined Wtp@Wself fp32 scratch
__device__ float g_wtp2[NLAYER*KTP*HDIM];               // 7 MB

// bf16 hi/lo transposed weights: [N][Kpad] per weight matrix
#define OFF_EMB   0
#define OFF_R2    32768
#define OFF_WTP   131072
#define OFF_WSELF 1900544   /* used as temp B for the combine GEMM */
#define OFF_WSKIP 2097152
#define BT_TOTAL  2293760
__device__ __nv_bfloat16 g_bhi[BT_TOTAL];
__device__ __nv_bfloat16 g_blo[BT_TOTAL];

// ---------------- small utility kernels ----------------
__global__ void zero_kernel() {
    int i = blockIdx.x*blockDim.x + threadIdx.x;
    if (i < N_NODES) g_deg[i] = 0;
    if (i < N_GRAPHS) { g_sums[i] = 0.0f; g_cnts[i] = 0.0f; }
}

__global__ void hist_kernel(const int* __restrict__ dst, const int* __restrict__ batch) {
    int i = blockIdx.x*blockDim.x + threadIdx.x;
    if (i < N_EDGES) atomicAdd(&g_deg[dst[i]], 1);
    if (i < N_NODES) atomicAdd(&g_cnts[batch[i]], 1.0f);
}

__global__ void scan_kernel() {
    __shared__ int s[1024];
    __shared__ int carry;
    int tid = threadIdx.x;
    if (tid == 0) carry = 0;
    __syncthreads();
    for (int base = 0; base < N_NODES; base += 1024) {
        int i = base + tid;
        int v = (i < N_NODES) ? g_deg[i] : 0;
        s[tid] = v;
        __syncthreads();
        for (int off = 1; off < 1024; off <<= 1) {
            int t = (tid >= off) ? s[tid-off] : 0;
            __syncthreads();
            if (tid >= off) s[tid] += t;
            __syncthreads();
        }
        int inc = s[tid] + carry;
        if (i < N_NODES) { g_rowptr[i+1] = inc; g_cursor[i] = inc - v; }
        if (i == 0) g_rowptr[0] = 0;
        __syncthreads();
        if (tid == 1023) carry = inc;
        __syncthreads();
    }
}

__global__ void build_csr_kernel(const int* __restrict__ dst) {
    int e = blockIdx.x*blockDim.x + threadIdx.x;
    if (e >= N_EDGES) return;
    int p = atomicAdd(&g_cursor[dst[e]], 1);
    g_csr[p] = e;
}

__global__ void edge_geom_kernel(const float* __restrict__ pos,
                                 const float* __restrict__ shift,
                                 const float* __restrict__ lattice,
                                 const int* __restrict__ batch,
                                 const int* __restrict__ src,
                                 const int* __restrict__ dst) {
    int e = blockIdx.x*blockDim.x + threadIdx.x;
    if (e >= N_EDGES) return;
    int s = src[e], d = dst[e];
    int b = batch[s];
    float sx = shift[e*3+0], sy = shift[e*3+1], sz = shift[e*3+2];
    const float* L = lattice + b*9;
    float v[3];
    #pragma unroll
    for (int j = 0; j < 3; j++)
        v[j] = pos[d*3+j] - pos[s*3+j] + sx*L[j] + sy*L[3+j] + sz*L[6+j];
    float len = sqrtf(v[0]*v[0] + v[1]*v[1] + v[2]*v[2]);
    float inv = 1.0f/(len + 1e-12f);
    float ux = v[0]*inv, uy = v[1]*inv, uz = v[2]*inv;
    const float c1 = 1.7320508075688772f;
    const float c2 = 3.872983346207417f;
    float* shp = g_sh + e*SH9;
    shp[0] = 1.0f;
    shp[1] = c1*ux;
    shp[2] = c1*uy;
    shp[3] = c1*uz;
    shp[4] = c2*ux*uy;
    shp[5] = c2*uy*uz;
    shp[6] = 1.118033988749895f*(3.0f*uz*uz - 1.0f);
    shp[7] = c2*ux*uz;
    shp[8] = 1.9364916731037085f*(ux*ux - uy*uy);
    const float step = 5.0f/11.0f;
    const float sq10 = 3.1622776601683795f;
    float* ep = g_emb + e*NB;
    #pragma unroll
    for (int i = 0; i < NB; i++) {
        float val = step*(float)(i+1);
        float diff = (len - val)/step;
        float em = 0.0f;
        if (diff > -1.0f && diff < 1.0f)
            em = cosf(1.5707963267948966f*diff)*sq10;
        ep[i] = em;
    }
}

// act = silu(emb @ r1 + b1), written pre-split bf16 hi/lo, K padded to 128
__global__ void act_kernel(const float* __restrict__ r1, const float* __restrict__ b1) {
    int w = (blockIdx.x*blockDim.x + threadIdx.x) >> 5;
    int lane = threadIdx.x & 31;
    if (w >= N_EDGES) return;
    float em[NB];
    const float* ep = g_emb + w*NB;
    #pragma unroll
    for (int i = 0; i < NB; i++) em[i] = ep[i];
    #pragma unroll
    for (int j = lane; j < 128; j += 32) {
        float val = 0.0f;
        if (j < RH) {
            float s = b1[j];
            #pragma unroll
            for (int i = 0; i < NB; i++) s += em[i]*r1[i*RH + j];
            val = s/(1.0f + expf(-s));
        }
        __nv_bfloat16 h = __float2bfloat16_rn(val);
        g_act_h[(size_t)w*128 + j] = h;
        g_act_l[(size_t)w*128 + j] = __float2bfloat16_rn(val - __bfloat162float(h));
    }
}

// scatter: G[n,a,k] = sum_{e: dst=n} sh[e,a]*h[src[e],k]*radial[e,k], written bf16 hi/lo
__global__ void __launch_bounds__(256) scatter_kernel(const float* __restrict__ h,
                                                      const int* __restrict__ src) {
    int n = blockIdx.x*8 + (threadIdx.x >> 5);
    int lane = threadIdx.x & 31;
    if (n >= N_NODES) return;
    float acc[SH9][8];
    #pragma unroll
    for (int a = 0; a < SH9; a++)
        #pragma unroll
        for (int k = 0; k < 8; k++) acc[a][k] = 0.0f;
    int beg = g_rowptr[n], end = g_rowptr[n+1];
    for (int idx = beg; idx < end; ++idx) {
        int e = g_csr[idx];
        int s = src[e];
        float shv[SH9];
        const float* sp = g_sh + e*SH9;
        #pragma unroll
        for (int a = 0; a < SH9; a++) shv[a] = sp[a];
        const float* hp = h + (size_t)s*HDIM + lane;
        const float* rp = g_radial + (size_t)e*HDIM + lane;
        #pragma unroll
        for (int k = 0; k < 8; k++) {
            float hs = hp[k*32]*rp[k*32];
            #pragma unroll
            for (int a = 0; a < SH9; a++) acc[a][k] += shv[a]*hs;
        }
    }
    __nv_bfloat16* gh = g_Gh + (size_t)n*KTP + lane;
    __nv_bfloat16* gl = g_Gl + (size_t)n*KTP + lane;
    #pragma unroll
    for (int a = 0; a < SH9; a++)
        #pragma unroll
        for (int k = 0; k < 8; k++) {
            float v = acc[a][k];
            __nv_bfloat16 hi = __float2bfloat16_rn(v);
            gh[a*HDIM + k*32] = hi;
            gl[a*HDIM + k*32] = __float2bfloat16_rn(v - __bfloat162float(hi));
        }
}

// ---------------- weight convert/transpose: B[K][N] fp32 -> Bt[N][Kpad] bf16 hi/lo ----------------
__global__ void convertB_kernel(const float* __restrict__ B,
                                __nv_bfloat16* __restrict__ hi,
                                __nv_bfloat16* __restrict__ lo,
                                int K, int Kpad, int N) {
    int i = blockIdx.x*blockDim.x + threadIdx.x;
    if (i >= N*Kpad) return;
    int n = i / Kpad, k = i - n*Kpad;
    float v = (k < K) ? B[(size_t)k*N + n] : 0.0f;
    __nv_bfloat16 h = __float2bfloat16_rn(v);
    hi[i] = h;
    lo[i] = __float2bfloat16_rn(v - __bfloat162float(h));
}

// ---------------- MMA helpers ----------------
__device__ __forceinline__ void mma16816(float* c, const uint32_t* a, const uint32_t* b) {
    asm volatile(
        "mma.sync.aligned.m16n8k16.row.col.f32.bf16.bf16.f32 "
        "{%0,%1,%2,%3}, {%4,%5,%6,%7}, {%8,%9}, {%0,%1,%2,%3};\n"
        : "+f"(c[0]), "+f"(c[1]), "+f"(c[2]), "+f"(c[3])
        : "r"(a[0]), "r"(a[1]), "r"(a[2]), "r"(a[3]), "r"(b[0]), "r"(b[1]));
}

__device__ __forceinline__ void ldsm_x4(uint32_t* r, uint32_t addr) {
    asm volatile("ldmatrix.sync.aligned.m8n8.x4.shared.b16 {%0,%1,%2,%3}, [%4];\n"
        : "=r"(r[0]), "=r"(r[1]), "=r"(r[2]), "=r"(r[3]) : "r"(addr));
}

__device__ __forceinline__ void cp16(uint32_t dst, const void* src) {
    asm volatile("cp.async.cg.shared.global [%0], [%1], 16;\n" :: "r"(dst), "l"(src));
}

__device__ __forceinline__ float gelu_f(float x) {
    float inner = 0.7978845608028654f*(x + 0.044715f*x*x*x);
    return 0.5f*x*(1.0f + tanhf(inner));
}

// ============ pre-split pipelined GEMM ============
// C[M,256] = alpha * (Ah+Al)[M,Kpad] @ (Bh+Bl)^T  (B stored [256][Kpad])
// 128x128x32 tiles, 3-stage cp.async, ldmatrix fragment loads, 3-term split MMA.
#define LDSB 40
#define STAGE_BYTES 40960   // 4 arrays * 128*40*2B
__global__ void __launch_bounds__(256, 1) mma_gemm_ps(int M, int Kpad,
    const __nv_bfloat16* __restrict__ Ah, const __nv_bfloat16* __restrict__ Al,
    const __nv_bfloat16* __restrict__ Bh, const __nv_bfloat16* __restrict__ Bl,
    float* __restrict__ C, float alpha)
{
    extern __shared__ char dsmem[];
    uint32_t smem_base = (uint32_t)__cvta_generic_to_shared(dsmem);

    int tid = threadIdx.x;
    int lane = tid & 31, warp = tid >> 5;
    int wm = (warp >> 2) * 64;
    int wn = (warp & 3) * 32;
    int bm = blockIdx.y * 128;
    int bn = blockIdx.x * 128;
    int nk = Kpad >> 5;

    float acc[4][4][4];
    #pragma unroll
    for (int i = 0; i < 4; i++)
        #pragma unroll
        for (int j = 0; j < 4; j++)
            #pragma unroll
            for (int r = 0; r < 4; r++) acc[i][j][r] = 0.0f;

    auto issue_load = [&](int ks) {
        int stage = ks % 3;
        uint32_t sb = smem_base + stage*STAGE_BYTES;
        int k0 = ks*32;
        #pragma unroll
        for (int c2 = 0; c2 < 2; c2++) {
            int c = tid + c2*256;
            int row = c >> 2, koff = (c & 3)*8;
            int ar = bm + row; if (ar > M-1) ar = M-1;
            size_t aoff = (size_t)ar*Kpad + k0 + koff;
            size_t boff = (size_t)(bn + row)*Kpad + k0 + koff;
            uint32_t d = sb + (uint32_t)(row*LDSB + koff)*2u;
            cp16(d,         Ah + aoff);
            cp16(d + 10240, Al + aoff);
            cp16(d + 20480, Bh + boff);
            cp16(d + 30720, Bl + boff);
        }
        asm volatile("cp.async.commit_group;\n" ::);
    };

    issue_load(0);
    if (nk > 1) issue_load(1);

    for (int ks = 0; ks < nk; ks++) {
        asm volatile("cp.async.wait_group 1;\n" ::);
        __syncthreads();
        if (ks + 2 < nk) issue_load(ks + 2);
        uint32_t sb = smem_base + (ks % 3)*STAGE_BYTES;

        #pragma unroll
        for (int kt = 0; kt < 2; kt++) {
            int c0 = kt*16;
            // B fragments: 2 ldmatrix.x4 per (hi,lo), covering nt pairs
            uint32_t bh[4][2], bl[4][2];
            #pragma unroll
            for (int ntp = 0; ntp < 2; ntp++) {
                int p = wn + ntp*16;
                int brow = p + (lane & 7) + (lane >> 4)*8;
                int bcol = c0 + ((lane >> 3) & 1)*8;
                uint32_t off = (uint32_t)(brow*LDSB + bcol)*2u;
                uint32_t rh[4], rl[4];
                ldsm_x4(rh, sb + 20480 + off);
                ldsm_x4(rl, sb + 30720 + off);
                bh[ntp*2+0][0] = rh[0]; bh[ntp*2+0][1] = rh[1];
                bh[ntp*2+1][0] = rh[2]; bh[ntp*2+1][1] = rh[3];
                bl[ntp*2+0][0] = rl[0]; bl[ntp*2+0][1] = rl[1];
                bl[ntp*2+1][0] = rl[2]; bl[ntp*2+1][1] = rl[3];
            }
            int arow_l = (lane & 7) + ((lane >> 3) & 1)*8;
            int acol_l = c0 + (lane >> 4)*8;
            #pragma unroll
            for (int mt = 0; mt < 4; mt++) {
                uint32_t off = (uint32_t)((wm + mt*16 + arow_l)*LDSB + acol_l)*2u;
                uint32_t ah[4], al[4];
                ldsm_x4(ah, sb + off);
                ldsm_x4(al, sb + 10240 + off);
                #pragma unroll
                for (int nt = 0; nt < 4; nt++) {
                    mma16816(acc[mt][nt], ah, bh[nt]);
                    mma16816(acc[mt][nt], ah, bl[nt]);
                    mma16816(acc[mt][nt], al, bh[nt]);
                }
            }
        }
        __syncthreads();
    }

    #pragma unroll
    for (int mt = 0; mt < 4; mt++) {
        int rbase = bm + wm + mt*16 + (lane >> 2);
        #pragma unroll
        for (int half = 0; half < 2; half++) {
            int rr = rbase + half*8;
            if (rr < M) {
                #pragma unroll
                for (int nt = 0; nt < 4; nt++) {
                    int cc = bn + wn + nt*8 + 2*(lane & 3);
                    float v0 = alpha*acc[mt][nt][half*2 + 0];
                    float v1 = alpha*acc[mt][nt][half*2 + 1];
                    *(float2*)(C + (size_t)rr*HDIM + cc) = make_float2(v0, v1);
                }
            }
        }
    }
}

// ============ fp32-A GEMM (R3 version, for small GEMMs: embed, skip, combine) ============
template<int ACT, int LOADC>
__global__ void __launch_bounds__(256, 1) mma_gemm(int M, int K, int Kpad,
    const float* __restrict__ A,
    const __nv_bfloat16* __restrict__ Bth,
    const __nv_bfloat16* __restrict__ Btl,
    float* __restrict__ C, float alpha)
{
    constexpr int N = 256;
    __shared__ uint16_t As_h[128*LDSB];
    __shared__ uint16_t As_l[128*LDSB];
    __shared__ uint16_t Bs_h[128*LDSB];
    __shared__ uint16_t Bs_l[128*LDSB];

    int tid = threadIdx.x;
    int lane = tid & 31, warp = tid >> 5;
    int wm = (warp >> 2) * 64;
    int wn = (warp & 3) * 32;
    int bm = blockIdx.y * 128;
    int bn = blockIdx.x * 128;

    float acc[4][4][4];
    #pragma unroll
    for (int i = 0; i < 4; i++)
        #pragma unroll
        for (int j = 0; j < 4; j++)
            #pragma unroll
            for (int r = 0; r < 4; r++) acc[i][j][r] = 0.0f;

    const int arow = tid >> 1, acb = (tid & 1) * 16;
    const int gm = bm + arow;
    const bool aok = gm < M;
    const bool kdiv4 = (K & 3) == 0;
    const int brow = tid >> 1, bcb = (tid & 1) * 16;

    float4 av[4];
    uint4 bhv[2], blv[2];

    auto fetchA = [&](int k0) {
        if (aok && kdiv4 && (k0 + acb + 16 <= K)) {
            const float* p = A + (size_t)gm*K + k0 + acb;
            av[0] = *(const float4*)(p);
            av[1] = *(const float4*)(p + 4);
            av[2] = *(const float4*)(p + 8);
            av[3] = *(const float4*)(p + 12);
        } else {
            const float* p = A + (size_t)gm*K;
            #pragma unroll
            for (int i = 0; i < 4; i++) {
                float t[4];
                #pragma unroll
                for (int j = 0; j < 4; j++) {
                    int kk = k0 + acb + i*4 + j;
                    t[j] = (aok && kk < K) ? p[kk] : 0.0f;
                }
                av[i] = make_float4(t[0], t[1], t[2], t[3]);
            }
        }
    };
    auto fetchB = [&](int k0) {
        const __nv_bfloat16* ph = Bth + (size_t)(bn + brow)*Kpad + k0 + bcb;
        const __nv_bfloat16* pl = Btl + (size_t)(bn + brow)*Kpad + k0 + bcb;
        bhv[0] = *(const uint4*)(ph);
        bhv[1] = *(const uint4*)(ph + 8);
        blv[0] = *(const uint4*)(pl);
        blv[1] = *(const uint4*)(pl + 8);
    };
    auto stage = [&]() {
        uint16_t* da = &As_h[arow*LDSB + acb];
        uint16_t* dal = &As_l[arow*LDSB + acb];
        #pragma unroll
        for (int i = 0; i < 4; i++) {
            float4 v = av[i];
            __nv_bfloat162 h01 = __floats2bfloat162_rn(v.x, v.y);
            __nv_bfloat162 h23 = __floats2bfloat162_rn(v.z, v.w);
            __nv_bfloat162 l01 = __floats2bfloat162_rn(v.x - __bfloat162float(h01.x),
                                                       v.y - __bfloat162float(h01.y));
            __nv_bfloat162 l23 = __floats2bfloat162_rn(v.z - __bfloat162float(h23.x),
                                                       v.w - __bfloat162float(h23.y));
            *(uint32_t*)(da + i*4)     = *(uint32_t*)&h01;
            *(uint32_t*)(da + i*4 + 2) = *(uint32_t*)&h23;
            *(uint32_t*)(dal + i*4)     = *(uint32_t*)&l01;
            *(uint32_t*)(dal + i*4 + 2) = *(uint32_t*)&l23;
        }
        uint16_t* db = &Bs_h[brow*LDSB + bcb];
        uint16_t* dbl = &Bs_l[brow*LDSB + bcb];
        *(uint2*)(db)      = make_uint2(bhv[0].x, bhv[0].y);
        *(uint2*)(db + 4)  = make_uint2(bhv[0].z, bhv[0].w);
        *(uint2*)(db + 8)  = make_uint2(bhv[1].x, bhv[1].y);
        *(uint2*)(db + 12) = make_uint2(bhv[1].z, bhv[1].w);
        *(uint2*)(dbl)      = make_uint2(blv[0].x, blv[0].y);
        *(uint2*)(dbl + 4)  = make_uint2(blv[0].z, blv[0].w);
        *(uint2*)(dbl + 8)  = make_uint2(blv[1].x, blv[1].y);
        *(uint2*)(dbl + 12) = make_uint2(blv[1].z, blv[1].w);
    };

    fetchA(0); fetchB(0);
    for (int k0 = 0; k0 < Kpad; k0 += 32) {
        stage();
        __syncthreads();
        if (k0 + 32 < Kpad) { fetchA(k0 + 32); fetchB(k0 + 32); }
        #pragma unroll
        for (int kt = 0; kt < 2; kt++) {
            int c = kt*16 + 2*(lane & 3);
            int r0 = lane >> 2;
            uint32_t bh[4][2], bl[4][2];
            #pragma unroll
            for (int nt = 0; nt < 4; nt++) {
                const uint16_t* pb  = &Bs_h[(wn + nt*8 + r0)*LDSB + c];
                const uint16_t* pbl = &Bs_l[(wn + nt*8 + r0)*LDSB + c];
                bh[nt][0] = *(const uint32_t*)(pb);
                bh[nt][1] = *(const uint32_t*)(pb + 8);
                bl[nt][0] = *(const uint32_t*)(pbl);
                bl[nt][1] = *(const uint32_t*)(pbl + 8);
            }
            #pragma unroll
            for (int mt = 0; mt < 4; mt++) {
                const uint16_t* pa  = &As_h[(wm + mt*16 + r0)*LDSB + c];
                const uint16_t* pal = &As_l[(wm + mt*16 + r0)*LDSB + c];
                uint32_t ah[4], al[4];
                ah[0] = *(const uint32_t*)(pa);
                ah[1] = *(const uint32_t*)(pa + 8*LDSB);
                ah[2] = *(const uint32_t*)(pa + 8);
                ah[3] = *(const uint32_t*)(pa + 8*LDSB + 8);
                al[0] = *(const uint32_t*)(pal);
                al[1] = *(const uint32_t*)(pal + 8*LDSB);
                al[2] = *(const uint32_t*)(pal + 8);
                al[3] = *(const uint32_t*)(pal + 8*LDSB + 8);
                #pragma unroll
                for (int nt = 0; nt < 4; nt++) {
                    mma16816(acc[mt][nt], ah, bh[nt]);
                    mma16816(acc[mt][nt], ah, bl[nt]);
                    mma16816(acc[mt][nt], al, bh[nt]);
                }
            }
        }
        __syncthreads();
    }

    #pragma unroll
    for (int mt = 0; mt < 4; mt++) {
        int rbase = bm + wm + mt*16 + (lane >> 2);
        #pragma unroll
        for (int half = 0; half < 2; half++) {
            int rr = rbase + half*8;
            if (rr < M) {
                #pragma unroll
                for (int nt = 0; nt < 4; nt++) {
                    int cc = bn + wn + nt*8 + 2*(lane & 3);
                    float v0 = alpha*acc[mt][nt][half*2 + 0];
                    float v1 = alpha*acc[mt][nt][half*2 + 1];
                    float* cp = C + (size_t)rr*N + cc;
                    if (LOADC) {
                        float2 old = *(const float2*)cp;
                        v0 += old.x; v1 += old.y;
                    }
                    if (ACT) { v0 = gelu_f(v0); v1 = gelu_f(v1); }
                    *(float2*)cp = make_float2(v0, v1);
                }
            }
        }
    }
}

// readout: node_out = h @ Wout, segment-sum by graph
__global__ void readout_kernel(const float* __restrict__ h,
                               const float* __restrict__ Wout,
                               const int* __restrict__ batch) {
    int n = blockIdx.x*8 + (threadIdx.x >> 5);
    int lane = threadIdx.x & 31;
    if (n >= N_NODES) return;
    float s = 0.0f;
    #pragma unroll
    for (int k = 0; k < 8; k++)
        s += h[(size_t)n*HDIM + k*32 + lane]*Wout[k*32 + lane];
    #pragma unroll
    for (int o = 16; o > 0; o >>= 1) s += __shfl_xor_sync(0xffffffffu, s, o);
    if (lane == 0) atomicAdd(&g_sums[batch[n]], s);
}

__global__ void finalize_kernel(float* __restrict__ out) {
    int g = threadIdx.x;
    if (g < N_GRAPHS) out[g] = g_sums[g]/fmaxf(g_cnts[g], 1.0f);
}

// ---------------- launch ----------------
extern "C" void kernel_launch(void* const* d_in, const int* in_sizes, int n_in,
                              void* d_out, int out_size) {
    (void)in_sizes; (void)n_in; (void)out_size;
    const float* x       = (const float*)d_in[0];
    const float* pos     = (const float*)d_in[1];
    const float* shift   = (const float*)d_in[2];
    const float* lattice = (const float*)d_in[3];
    const float* W_embed = (const float*)d_in[4];
    const float* r1      = (const float*)d_in[5];
    const float* b1      = (const float*)d_in[6];
    const float* r2      = (const float*)d_in[7];
    const float* Wtp     = (const float*)d_in[8];
    const float* Wself   = (const float*)d_in[9];
    const float* Wskip   = (const float*)d_in[10];
    const float* Wout    = (const float*)d_in[11];
    const int*   eidx    = (const int*)d_in[12];
    const int*   batch   = (const int*)d_in[13];
    const int* esrc = eidx;
    const int* edst = eidx + N_EDGES;
    float* out = (float*)d_out;

    float *hA, *hB, *radial, *wtp2;
    __nv_bfloat16 *bhi, *blo, *acth, *actl, *Gh, *Gl;
    cudaGetSymbolAddress((void**)&hA,     g_hA);
    cudaGetSymbolAddress((void**)&hB,     g_hB);
    cudaGetSymbolAddress((void**)&radial, g_radial);
    cudaGetSymbolAddress((void**)&wtp2,   g_wtp2);
    cudaGetSymbolAddress((void**)&bhi,    g_bhi);
    cudaGetSymbolAddress((void**)&blo,    g_blo);
    cudaGetSymbolAddress((void**)&acth,   g_act_h);
    cudaGetSymbolAddress((void**)&actl,   g_act_l);
    cudaGetSymbolAddress((void**)&Gh,     g_Gh);
    cudaGetSymbolAddress((void**)&Gl,     g_Gl);

    cudaFuncSetAttribute(mma_gemm_ps, cudaFuncAttributeMaxDynamicSharedMemorySize, 3*STAGE_BYTES);

    const int TB = 256;
    zero_kernel<<<(N_NODES + TB - 1)/TB, TB>>>();
    hist_kernel<<<(N_EDGES + TB - 1)/TB, TB>>>(edst, batch);
    scan_kernel<<<1, 1024>>>();
    build_csr_kernel<<<(N_EDGES + TB - 1)/TB, TB>>>(edst);
    edge_geom_kernel<<<(N_EDGES + TB - 1)/TB, TB>>>(pos, shift, lattice, batch, esrc, edst);

    auto cvt = [&](const float* B, int off, int K, int Kpad) {
        int n = HDIM*Kpad;
        convertB_kernel<<<(n + TB - 1)/TB, TB>>>(B, bhi + off, blo + off, K, Kpad, HDIM);
    };
    const float inv_sqrt_deg = 0.28867513459481287f;  // 1/sqrt(12)

    cvt(W_embed, OFF_EMB, D_IN, 128);
    for (int l = 0; l < NLAYER; l++) {
        cvt(r2 + (size_t)l*RH*HDIM,      OFF_R2    + l*32768, RH,   128);
        cvt(Wskip + (size_t)l*HDIM*HDIM, OFF_WSKIP + l*65536, HDIM, 256);
        // combined Wtp' = inv_sqrt_deg * Wtp_flat @ Wself
        cvt(Wself + (size_t)l*HDIM*HDIM, OFF_WSELF, HDIM, 256);
        dim3 gComb(2, KTP/128);   // (2, 18)
        mma_gemm<0,0><<<gComb, 256>>>(KTP, HDIM, 256, Wtp + (size_t)l*KTP*HDIM,
                                      bhi + OFF_WSELF, blo + OFF_WSELF,
                                      wtp2 + (size_t)l*KTP*HDIM, inv_sqrt_deg);
        cvt(wtp2 + (size_t)l*KTP*HDIM, OFF_WTP + l*589824, KTP, 2304);
    }

    dim3 gNode(2, (N_NODES + 127)/128);   // (2, 157)
    dim3 gEdge(2, N_EDGES/128);           // (2, 1875)

    // h = x @ W_embed
    mma_gemm<0,0><<<gNode, 256>>>(N_NODES, D_IN, 128, x, bhi + OFF_EMB, blo + OFF_EMB, hA, 1.0f);

    float* hc = hA;
    float* hn = hB;

    for (int l = 0; l < NLAYER; l++) {
        act_kernel<<<(N_EDGES + 7)/8, 256>>>(r1 + l*NB*RH, b1 + l*RH);
        // radial = act @ r2[l]
        mma_gemm_ps<<<gEdge, 256, 3*STAGE_BYTES>>>(N_EDGES, 128, acth, actl,
            bhi + OFF_R2 + l*32768, blo + OFF_R2 + l*32768, radial, 1.0f);
        scatter_kernel<<<(N_NODES + 7)/8, 256>>>(hc, esrc);
        // hn = G @ Wtp'   (Wself + 1/sqrt(12) folded in)
        mma_gemm_ps<<<gNode, 256, 3*STAGE_BYTES>>>(N_NODES, 2304, Gh, Gl,
            bhi + OFF_WTP + l*589824, blo + OFF_WTP + l*589824, hn, 1.0f);
        // hn = gelu(hn + h @ Wskip[l])
        mma_gemm<1,1><<<gNode, 256>>>(N_NODES, HDIM, 256, hc,
                                      bhi + OFF_WSKIP + l*65536, blo + OFF_WSKIP + l*65536,
                                      hn, 1.0f);
        float* t = hc; hc = hn; hn = t;
    }

    readout_kernel<<<(N_NODES + 7)/8, 256>>>(hc, Wout, batch);
    finalize_kernel<<<1, 256>>>(out);
}

// round 10
// speedup vs baseline: 2.7423x; 1.1451x over previous
#include <cuda_runtime.h>
#include <cuda_bf16.h>
#include <cuda_fp16.h>
#include <math.h>
#include <stdint.h>

#define N_NODES 20000
#define N_EDGES 240000
#define N_GRAPHS 200
#define D_IN 118
#define HDIM 256
#define NB 10
#define RH 100
#define NLAYER 3
#define SH9 9
#define KTP (SH9*HDIM)   // 2304
#define KPAD2 2560       // KTP + 256 (h tail for fused skip)

// ---------------- static device scratch (no allocation allowed) ----------------
__device__ float g_hA[N_NODES*HDIM];
__device__ float g_hB[N_NODES*HDIM];
__device__ float g_sh[N_EDGES*SH9];
__device__ float g_emb[N_EDGES*NB];
__device__ int   g_deg[N_NODES];
__device__ int   g_rowptr[N_NODES+1];
__device__ int   g_cursor[N_NODES];
__device__ int   g_csr[N_EDGES];
__device__ float g_sums[N_GRAPHS];
__device__ float g_cnts[N_GRAPHS];

__device__ __half        g_radial_h[(size_t)N_EDGES*HDIM];   // 123 MB
__device__ __nv_bfloat16 g_act_h[(size_t)N_EDGES*128];       // 61 MB
__device__ __nv_bfloat16 g_act_l[(size_t)N_EDGES*128];       // 61 MB
__device__ __nv_bfloat16 g_Gh[(size_t)N_NODES*KPAD2];        // 102 MB
__device__ __nv_bfloat16 g_Gl[(size_t)N_NODES*KPAD2];        // 102 MB
__device__ float g_wtp2[NLAYER*KTP*HDIM];                    // 7 MB

// bf16 hi/lo transposed weights, [N][stride] layouts
#define OFF_EMB    0
#define OFF_R2     32768            /* + l*32768 */
#define OFF_WCOMB  131072           /* + l*655360 ; [256][2560]: Wtp' cols 0..2303, Wskip 2304..2559 */
#define OFF_WSELFT 2097152          /* temp [256][256] for combine GEMM */
#define BT_TOTAL   2293760
__device__ __nv_bfloat16 g_bhi[BT_TOTAL];
__device__ __nv_bfloat16 g_blo[BT_TOTAL];

// ---------------- small utility kernels ----------------
__global__ void zero_kernel() {
    int i = blockIdx.x*blockDim.x + threadIdx.x;
    if (i < N_NODES) g_deg[i] = 0;
    if (i < N_GRAPHS) { g_sums[i] = 0.0f; g_cnts[i] = 0.0f; }
}

__global__ void hist_kernel(const int* __restrict__ dst, const int* __restrict__ batch) {
    int i = blockIdx.x*blockDim.x + threadIdx.x;
    if (i < N_EDGES) atomicAdd(&g_deg[dst[i]], 1);
    if (i < N_NODES) atomicAdd(&g_cnts[batch[i]], 1.0f);
}

__global__ void scan_kernel() {
    __shared__ int s[1024];
    __shared__ int carry;
    int tid = threadIdx.x;
    if (tid == 0) carry = 0;
    __syncthreads();
    for (int base = 0; base < N_NODES; base += 1024) {
        int i = base + tid;
        int v = (i < N_NODES) ? g_deg[i] : 0;
        s[tid] = v;
        __syncthreads();
        for (int off = 1; off < 1024; off <<= 1) {
            int t = (tid >= off) ? s[tid-off] : 0;
            __syncthreads();
            if (tid >= off) s[tid] += t;
            __syncthreads();
        }
        int inc = s[tid] + carry;
        if (i < N_NODES) { g_rowptr[i+1] = inc; g_cursor[i] = inc - v; }
        if (i == 0) g_rowptr[0] = 0;
        __syncthreads();
        if (tid == 1023) carry = inc;
        __syncthreads();
    }
}

__global__ void build_csr_kernel(const int* __restrict__ dst) {
    int e = blockIdx.x*blockDim.x + threadIdx.x;
    if (e >= N_EDGES) return;
    int p = atomicAdd(&g_cursor[dst[e]], 1);
    g_csr[p] = e;
}

__global__ void edge_geom_kernel(const float* __restrict__ pos,
                                 const float* __restrict__ shift,
                                 const float* __restrict__ lattice,
                                 const int* __restrict__ batch,
                                 const int* __restrict__ src,
                                 const int* __restrict__ dst) {
    int e = blockIdx.x*blockDim.x + threadIdx.x;
    if (e >= N_EDGES) return;
    int s = src[e], d = dst[e];
    int b = batch[s];
    float sx = shift[e*3+0], sy = shift[e*3+1], sz = shift[e*3+2];
    const float* L = lattice + b*9;
    float v[3];
    #pragma unroll
    for (int j = 0; j < 3; j++)
        v[j] = pos[d*3+j] - pos[s*3+j] + sx*L[j] + sy*L[3+j] + sz*L[6+j];
    float len = sqrtf(v[0]*v[0] + v[1]*v[1] + v[2]*v[2]);
    float inv = 1.0f/(len + 1e-12f);
    float ux = v[0]*inv, uy = v[1]*inv, uz = v[2]*inv;
    const float c1 = 1.7320508075688772f;
    const float c2 = 3.872983346207417f;
    float* shp = g_sh + e*SH9;
    shp[0] = 1.0f;
    shp[1] = c1*ux;
    shp[2] = c1*uy;
    shp[3] = c1*uz;
    shp[4] = c2*ux*uy;
    shp[5] = c2*uy*uz;
    shp[6] = 1.118033988749895f*(3.0f*uz*uz - 1.0f);
    shp[7] = c2*ux*uz;
    shp[8] = 1.9364916731037085f*(ux*ux - uy*uy);
    const float step = 5.0f/11.0f;
    const float sq10 = 3.1622776601683795f;
    float* ep = g_emb + e*NB;
    #pragma unroll
    for (int i = 0; i < NB; i++) {
        float val = step*(float)(i+1);
        float diff = (len - val)/step;
        float em = 0.0f;
        if (diff > -1.0f && diff < 1.0f)
            em = cosf(1.5707963267948966f*diff)*sq10;
        ep[i] = em;
    }
}

// act = silu(emb @ r1 + b1), written pre-split bf16 hi/lo, K padded to 128
__global__ void act_kernel(const float* __restrict__ r1, const float* __restrict__ b1) {
    int w = (blockIdx.x*blockDim.x + threadIdx.x) >> 5;
    int lane = threadIdx.x & 31;
    if (w >= N_EDGES) return;
    float em[NB];
    const float* ep = g_emb + w*NB;
    #pragma unroll
    for (int i = 0; i < NB; i++) em[i] = ep[i];
    #pragma unroll
    for (int j = lane; j < 128; j += 32) {
        float val = 0.0f;
        if (j < RH) {
            float s = b1[j];
            #pragma unroll
            for (int i = 0; i < NB; i++) s += em[i]*r1[i*RH + j];
            val = s/(1.0f + expf(-s));
        }
        __nv_bfloat16 h = __float2bfloat16_rn(val);
        g_act_h[(size_t)w*128 + j] = h;
        g_act_l[(size_t)w*128 + j] = __float2bfloat16_rn(val - __bfloat162float(h));
    }
}

// scatter: G[n, a*256+k] = sum_{e: dst=n} sh[e,a]*h[src[e],k]*radial[e,k]  (cols 0..2303, stride KPAD2)
__global__ void __launch_bounds__(256) scatter_kernel(const float* __restrict__ h,
                                                      const int* __restrict__ src) {
    int n = blockIdx.x*8 + (threadIdx.x >> 5);
    int lane = threadIdx.x & 31;
    if (n >= N_NODES) return;
    float acc[SH9][4][2];
    #pragma unroll
    for (int a = 0; a < SH9; a++)
        #pragma unroll
        for (int j = 0; j < 4; j++) { acc[a][j][0] = 0.0f; acc[a][j][1] = 0.0f; }
    int beg = g_rowptr[n], end = g_rowptr[n+1];
    for (int idx = beg; idx < end; ++idx) {
        int e = g_csr[idx];
        int s = src[e];
        float shv[SH9];
        const float* sp = g_sh + e*SH9;
        #pragma unroll
        for (int a = 0; a < SH9; a++) shv[a] = sp[a];
        const float* hp = h + (size_t)s*HDIM;
        const __half* rp = g_radial_h + (size_t)e*HDIM;
        #pragma unroll
        for (int j = 0; j < 4; j++) {
            int k = j*64 + lane*2;
            float2 hv = *(const float2*)(hp + k);
            float2 rf = __half22float2(*(const __half2*)(rp + k));
            float hs0 = hv.x*rf.x;
            float hs1 = hv.y*rf.y;
            #pragma unroll
            for (int a = 0; a < SH9; a++) {
                acc[a][j][0] += shv[a]*hs0;
                acc[a][j][1] += shv[a]*hs1;
            }
        }
    }
    __nv_bfloat16* gh = g_Gh + (size_t)n*KPAD2;
    __nv_bfloat16* gl = g_Gl + (size_t)n*KPAD2;
    #pragma unroll
    for (int a = 0; a < SH9; a++)
        #pragma unroll
        for (int j = 0; j < 4; j++) {
            int k = a*256 + j*64 + lane*2;
            float v0 = acc[a][j][0], v1 = acc[a][j][1];
            __nv_bfloat162 hi = __floats2bfloat162_rn(v0, v1);
            __nv_bfloat162 lo = __floats2bfloat162_rn(v0 - __bfloat162float(hi.x),
                                                      v1 - __bfloat162float(hi.y));
            *(__nv_bfloat162*)(gh + k) = hi;
            *(__nv_bfloat162*)(gl + k) = lo;
        }
}

// write split(h) into G tail cols [KTP, KTP+256)
__global__ void splitH_kernel(const float* __restrict__ h) {
    int i = blockIdx.x*blockDim.x + threadIdx.x;
    if (i >= N_NODES*HDIM) return;
    int n = i >> 8, k = i & 255;
    float v = h[i];
    __nv_bfloat16 hi = __float2bfloat16_rn(v);
    g_Gh[(size_t)n*KPAD2 + KTP + k] = hi;
    g_Gl[(size_t)n*KPAD2 + KTP + k] = __float2bfloat16_rn(v - __bfloat162float(hi));
}

// ---------------- weight convert/transpose ----------------
// B[K][N] fp32 -> dst[n*dstStride + dstOff + k] bf16 hi/lo, k in [0, Kcols), zero-pad k>=K
__global__ void convertB_kernel(const float* __restrict__ B,
                                __nv_bfloat16* __restrict__ hi,
                                __nv_bfloat16* __restrict__ lo,
                                int K, int Kcols, int dstStride, int dstOff, int N) {
    int i = blockIdx.x*blockDim.x + threadIdx.x;
    if (i >= N*Kcols) return;
    int n = i / Kcols, k = i - n*Kcols;
    float v = (k < K) ? B[(size_t)k*N + n] : 0.0f;
    __nv_bfloat16 h = __float2bfloat16_rn(v);
    size_t di = (size_t)n*dstStride + dstOff + k;
    hi[di] = h;
    lo[di] = __float2bfloat16_rn(v - __bfloat162float(h));
}

// ---------------- MMA helpers ----------------
__device__ __forceinline__ void mma16816(float* c, const uint32_t* a, const uint32_t* b) {
    asm volatile(
        "mma.sync.aligned.m16n8k16.row.col.f32.bf16.bf16.f32 "
        "{%0,%1,%2,%3}, {%4,%5,%6,%7}, {%8,%9}, {%0,%1,%2,%3};\n"
        : "+f"(c[0]), "+f"(c[1]), "+f"(c[2]), "+f"(c[3])
        : "r"(a[0]), "r"(a[1]), "r"(a[2]), "r"(a[3]), "r"(b[0]), "r"(b[1]));
}

__device__ __forceinline__ void ldsm_x4(uint32_t* r, uint32_t addr) {
    asm volatile("ldmatrix.sync.aligned.m8n8.x4.shared.b16 {%0,%1,%2,%3}, [%4];\n"
        : "=r"(r[0]), "=r"(r[1]), "=r"(r[2]), "=r"(r[3]) : "r"(addr));
}

__device__ __forceinline__ void cp16(uint32_t dst, const void* src) {
    asm volatile("cp.async.cg.shared.global [%0], [%1], 16;\n" :: "r"(dst), "l"(src));
}

__device__ __forceinline__ float gelu_f(float x) {
    float inner = 0.7978845608028654f*(x + 0.044715f*x*x*x);
    return 0.5f*x*(1.0f + tanhf(inner));
}

// ============ pre-split pipelined GEMM: 64x128x32, 3-stage cp.async ============
// C[M,256] = actf(alpha * (Ah[+Al])[M,Kpad] @ (Bh+Bl)^T), B stored [256][Kpad]
// TERMS: 2 = Ah only (2 MMA terms), 3 = Ah+Al (3 MMA terms)
// OUTHALF: store __half; ACTG: gelu
#define LDSB 40
#define SSTAGE 30720   // Ah 5120 | Al 5120 | Bh 10240 | Bl 10240
template<int TERMS, int OUTHALF, int ACTG>
__global__ void __launch_bounds__(256, 2) mma_gemm_ps(int M, int Kpad,
    const __nv_bfloat16* __restrict__ Ah, const __nv_bfloat16* __restrict__ Al,
    const __nv_bfloat16* __restrict__ Bh, const __nv_bfloat16* __restrict__ Bl,
    void* __restrict__ Cout, float alpha)
{
    extern __shared__ char dsmem[];
    uint32_t smem_base = (uint32_t)__cvta_generic_to_shared(dsmem);

    int tid = threadIdx.x;
    int lane = tid & 31, warp = tid >> 5;
    int wm = (warp >> 2) * 32;
    int wn = (warp & 3) * 32;
    int bm = blockIdx.y * 64;
    int bn = blockIdx.x * 128;
    int nk = Kpad >> 5;

    float acc[2][4][4];
    #pragma unroll
    for (int i = 0; i < 2; i++)
        #pragma unroll
        for (int j = 0; j < 4; j++)
            #pragma unroll
            for (int r = 0; r < 4; r++) acc[i][j][r] = 0.0f;

    auto issue_load = [&](int ks) {
        uint32_t sb = smem_base + (ks % 3)*SSTAGE;
        int k0 = ks*32;
        // A: 64 rows x 32 cols, one 16B chunk per thread
        {
            int row = tid >> 2, koff = (tid & 3)*8;
            int ar = bm + row; if (ar > M-1) ar = M-1;
            size_t aoff = (size_t)ar*Kpad + k0 + koff;
            uint32_t da = sb + (uint32_t)(row*LDSB + koff)*2u;
            cp16(da, Ah + aoff);
            if (TERMS == 3) cp16(da + 5120, Al + aoff);
        }
        // B: 128 rows x 32 cols, two 16B chunks per thread
        #pragma unroll
        for (int c2 = 0; c2 < 2; c2++) {
            int c = tid + c2*256;
            int row = c >> 2, koff = (c & 3)*8;
            size_t boff = (size_t)(bn + row)*Kpad + k0 + koff;
            uint32_t db = sb + 10240 + (uint32_t)(row*LDSB + koff)*2u;
            cp16(db, Bh + boff);
            cp16(db + 10240, Bl + boff);
        }
        asm volatile("cp.async.commit_group;\n" ::);
    };

    issue_load(0);
    issue_load(1);

    for (int ks = 0; ks < nk; ks++) {
        asm volatile("cp.async.wait_group 1;\n" ::);
        __syncthreads();
        if (ks + 2 < nk) issue_load(ks + 2);
        uint32_t sb = smem_base + (ks % 3)*SSTAGE;

        #pragma unroll
        for (int kt = 0; kt < 2; kt++) {
            int c0 = kt*16;
            uint32_t bh[4][2], bl[4][2];
            #pragma unroll
            for (int ntp = 0; ntp < 2; ntp++) {
                int brow = wn + ntp*16 + (lane & 7) + (lane >> 4)*8;
                int bcol = c0 + ((lane >> 3) & 1)*8;
                uint32_t off = 10240u + (uint32_t)(brow*LDSB + bcol)*2u;
                uint32_t rh[4], rl[4];
                ldsm_x4(rh, sb + off);
                ldsm_x4(rl, sb + off + 10240);
                bh[ntp*2+0][0] = rh[0]; bh[ntp*2+0][1] = rh[1];
                bh[ntp*2+1][0] = rh[2]; bh[ntp*2+1][1] = rh[3];
                bl[ntp*2+0][0] = rl[0]; bl[ntp*2+0][1] = rl[1];
                bl[ntp*2+1][0] = rl[2]; bl[ntp*2+1][1] = rl[3];
            }
            int arow_l = (lane & 7) + ((lane >> 3) & 1)*8;
            int acol_l = c0 + (lane >> 4)*8;
            #pragma unroll
            for (int mt = 0; mt < 2; mt++) {
                uint32_t off = (uint32_t)((wm + mt*16 + arow_l)*LDSB + acol_l)*2u;
                uint32_t ah[4], al[4];
                ldsm_x4(ah, sb + off);
                if (TERMS == 3) ldsm_x4(al, sb + 5120 + off);
                #pragma unroll
                for (int nt = 0; nt < 4; nt++) {
                    mma16816(acc[mt][nt], ah, bh[nt]);
                    mma16816(acc[mt][nt], ah, bl[nt]);
                    if (TERMS == 3) mma16816(acc[mt][nt], al, bh[nt]);
                }
            }
        }
        __syncthreads();
    }

    #pragma unroll
    for (int mt = 0; mt < 2; mt++) {
        int rbase = bm + wm + mt*16 + (lane >> 2);
        #pragma unroll
        for (int half = 0; half < 2; half++) {
            int rr = rbase + half*8;
            if (rr < M) {
                #pragma unroll
                for (int nt = 0; nt < 4; nt++) {
                    int cc = bn + wn + nt*8 + 2*(lane & 3);
                    float v0 = alpha*acc[mt][nt][half*2 + 0];
                    float v1 = alpha*acc[mt][nt][half*2 + 1];
                    if (ACTG) { v0 = gelu_f(v0); v1 = gelu_f(v1); }
                    if (OUTHALF) {
                        *(__half2*)((__half*)Cout + (size_t)rr*HDIM + cc) = __floats2half2_rn(v0, v1);
                    } else {
                        *(float2*)((float*)Cout + (size_t)rr*HDIM + cc) = make_float2(v0, v1);
                    }
                }
            }
        }
    }
}

// ============ fp32-A GEMM (embed + weight-combine) ============
__global__ void __launch_bounds__(256, 1) mma_gemm(int M, int K, int Kpad,
    const float* __restrict__ A,
    const __nv_bfloat16* __restrict__ Bth,
    const __nv_bfloat16* __restrict__ Btl,
    float* __restrict__ C, float alpha)
{
    constexpr int N = 256;
    __shared__ uint16_t As_h[128*LDSB];
    __shared__ uint16_t As_l[128*LDSB];
    __shared__ uint16_t Bs_h[128*LDSB];
    __shared__ uint16_t Bs_l[128*LDSB];

    int tid = threadIdx.x;
    int lane = tid & 31, warp = tid >> 5;
    int wm = (warp >> 2) * 64;
    int wn = (warp & 3) * 32;
    int bm = blockIdx.y * 128;
    int bn = blockIdx.x * 128;

    float acc[4][4][4];
    #pragma unroll
    for (int i = 0; i < 4; i++)
        #pragma unroll
        for (int j = 0; j < 4; j++)
            #pragma unroll
            for (int r = 0; r < 4; r++) acc[i][j][r] = 0.0f;

    const int arow = tid >> 1, acb = (tid & 1) * 16;
    const int gm = bm + arow;
    const bool aok = gm < M;
    const bool kdiv4 = (K & 3) == 0;
    const int brow = tid >> 1, bcb = (tid & 1) * 16;

    float4 av[4];
    uint4 bhv[2], blv[2];

    auto fetchA = [&](int k0) {
        if (aok && kdiv4 && (k0 + acb + 16 <= K)) {
            const float* p = A + (size_t)gm*K + k0 + acb;
            av[0] = *(const float4*)(p);
            av[1] = *(const float4*)(p + 4);
            av[2] = *(const float4*)(p + 8);
            av[3] = *(const float4*)(p + 12);
        } else {
            const float* p = A + (size_t)gm*K;
            #pragma unroll
            for (int i = 0; i < 4; i++) {
                float t[4];
                #pragma unroll
                for (int j = 0; j < 4; j++) {
                    int kk = k0 + acb + i*4 + j;
                    t[j] = (aok && kk < K) ? p[kk] : 0.0f;
                }
                av[i] = make_float4(t[0], t[1], t[2], t[3]);
            }
        }
    };
    auto fetchB = [&](int k0) {
        const __nv_bfloat16* ph = Bth + (size_t)(bn + brow)*Kpad + k0 + bcb;
        const __nv_bfloat16* pl = Btl + (size_t)(bn + brow)*Kpad + k0 + bcb;
        bhv[0] = *(const uint4*)(ph);
        bhv[1] = *(const uint4*)(ph + 8);
        blv[0] = *(const uint4*)(pl);
        blv[1] = *(const uint4*)(pl + 8);
    };
    auto stage = [&]() {
        uint16_t* da = &As_h[arow*LDSB + acb];
        uint16_t* dal = &As_l[arow*LDSB + acb];
        #pragma unroll
        for (int i = 0; i < 4; i++) {
            float4 v = av[i];
            __nv_bfloat162 h01 = __floats2bfloat162_rn(v.x, v.y);
            __nv_bfloat162 h23 = __floats2bfloat162_rn(v.z, v.w);
            __nv_bfloat162 l01 = __floats2bfloat162_rn(v.x - __bfloat162float(h01.x),
                                                       v.y - __bfloat162float(h01.y));
            __nv_bfloat162 l23 = __floats2bfloat162_rn(v.z - __bfloat162float(h23.x),
                                                       v.w - __bfloat162float(h23.y));
            *(uint32_t*)(da + i*4)     = *(uint32_t*)&h01;
            *(uint32_t*)(da + i*4 + 2) = *(uint32_t*)&h23;
            *(uint32_t*)(dal + i*4)     = *(uint32_t*)&l01;
            *(uint32_t*)(dal + i*4 + 2) = *(uint32_t*)&l23;
        }
        uint16_t* db = &Bs_h[brow*LDSB + bcb];
        uint16_t* dbl = &Bs_l[brow*LDSB + bcb];
        *(uint2*)(db)      = make_uint2(bhv[0].x, bhv[0].y);
        *(uint2*)(db + 4)  = make_uint2(bhv[0].z, bhv[0].w);
        *(uint2*)(db + 8)  = make_uint2(bhv[1].x, bhv[1].y);
        *(uint2*)(db + 12) = make_uint2(bhv[1].z, bhv[1].w);
        *(uint2*)(dbl)      = make_uint2(blv[0].x, blv[0].y);
        *(uint2*)(dbl + 4)  = make_uint2(blv[0].z, blv[0].w);
        *(uint2*)(dbl + 8)  = make_uint2(blv[1].x, blv[1].y);
        *(uint2*)(dbl + 12) = make_uint2(blv[1].z, blv[1].w);
    };

    fetchA(0); fetchB(0);
    for (int k0 = 0; k0 < Kpad; k0 += 32) {
        stage();
        __syncthreads();
        if (k0 + 32 < Kpad) { fetchA(k0 + 32); fetchB(k0 + 32); }
        #pragma unroll
        for (int kt = 0; kt < 2; kt++) {
            int c = kt*16 + 2*(lane & 3);
            int r0 = lane >> 2;
            uint32_t bh[4][2], bl[4][2];
            #pragma unroll
            for (int nt = 0; nt < 4; nt++) {
                const uint16_t* pb  = &Bs_h[(wn + nt*8 + r0)*LDSB + c];
                const uint16_t* pbl = &Bs_l[(wn + nt*8 + r0)*LDSB + c];
                bh[nt][0] = *(const uint32_t*)(pb);
                bh[nt][1] = *(const uint32_t*)(pb + 8);
                bl[nt][0] = *(const uint32_t*)(pbl);
                bl[nt][1] = *(const uint32_t*)(pbl + 8);
            }
            #pragma unroll
            for (int mt = 0; mt < 4; mt++) {
                const uint16_t* pa  = &As_h[(wm + mt*16 + r0)*LDSB + c];
                const uint16_t* pal = &As_l[(wm + mt*16 + r0)*LDSB + c];
                uint32_t ah[4], al[4];
                ah[0] = *(const uint32_t*)(pa);
                ah[1] = *(const uint32_t*)(pa + 8*LDSB);
                ah[2] = *(const uint32_t*)(pa + 8);
                ah[3] = *(const uint32_t*)(pa + 8*LDSB + 8);
                al[0] = *(const uint32_t*)(pal);
                al[1] = *(const uint32_t*)(pal + 8*LDSB);
                al[2] = *(const uint32_t*)(pal + 8);
                al[3] = *(const uint32_t*)(pal + 8*LDSB + 8);
                #pragma unroll
                for (int nt = 0; nt < 4; nt++) {
                    mma16816(acc[mt][nt], ah, bh[nt]);
                    mma16816(acc[mt][nt], ah, bl[nt]);
                    mma16816(acc[mt][nt], al, bh[nt]);
                }
            }
        }
        __syncthreads();
    }

    #pragma unroll
    for (int mt = 0; mt < 4; mt++) {
        int rbase = bm + wm + mt*16 + (lane >> 2);
        #pragma unroll
        for (int half = 0; half < 2; half++) {
            int rr = rbase + half*8;
            if (rr < M) {
                #pragma unroll
                for (int nt = 0; nt < 4; nt++) {
                    int cc = bn + wn + nt*8 + 2*(lane & 3);
                    float v0 = alpha*acc[mt][nt][half*2 + 0];
                    float v1 = alpha*acc[mt][nt][half*2 + 1];
                    *(float2*)(C + (size_t)rr*N + cc) = make_float2(v0, v1);
                }
            }
        }
    }
}

// readout: node_out = h @ Wout, segment-sum by graph
__global__ void readout_kernel(const float* __restrict__ h,
                               const float* __restrict__ Wout,
                               const int* __restrict__ batch) {
    int n = blockIdx.x*8 + (threadIdx.x >> 5);
    int lane = threadIdx.x & 31;
    if (n >= N_NODES) return;
    float s = 0.0f;
    #pragma unroll
    for (int k = 0; k < 8; k++)
        s += h[(size_t)n*HDIM + k*32 + lane]*Wout[k*32 + lane];
    #pragma unroll
    for (int o = 16; o > 0; o >>= 1) s += __shfl_xor_sync(0xffffffffu, s, o);
    if (lane == 0) atomicAdd(&g_sums[batch[n]], s);
}

__global__ void finalize_kernel(float* __restrict__ out) {
    int g = threadIdx.x;
    if (g < N_GRAPHS) out[g] = g_sums[g]/fmaxf(g_cnts[g], 1.0f);
}

// ---------------- launch ----------------
extern "C" void kernel_launch(void* const* d_in, const int* in_sizes, int n_in,
                              void* d_out, int out_size) {
    (void)in_sizes; (void)n_in; (void)out_size;
    const float* x       = (const float*)d_in[0];
    const float* pos     = (const float*)d_in[1];
    const float* shift   = (const float*)d_in[2];
    const float* lattice = (const float*)d_in[3];
    const float* W_embed = (const float*)d_in[4];
    const float* r1      = (const float*)d_in[5];
    const float* b1      = (const float*)d_in[6];
    const float* r2      = (const float*)d_in[7];
    const float* Wtp     = (const float*)d_in[8];
    const float* Wself   = (const float*)d_in[9];
    const float* Wskip   = (const float*)d_in[10];
    const float* Wout    = (const float*)d_in[11];
    const int*   eidx    = (const int*)d_in[12];
    const int*   batch   = (const int*)d_in[13];
    const int* esrc = eidx;
    const int* edst = eidx + N_EDGES;
    float* out = (float*)d_out;

    float *hA, *hB, *wtp2;
    __nv_bfloat16 *bhi, *blo, *acth, *actl, *Gh, *Gl;
    __half *radialh;
    cudaGetSymbolAddress((void**)&hA,      g_hA);
    cudaGetSymbolAddress((void**)&hB,      g_hB);
    cudaGetSymbolAddress((void**)&wtp2,    g_wtp2);
    cudaGetSymbolAddress((void**)&bhi,     g_bhi);
    cudaGetSymbolAddress((void**)&blo,     g_blo);
    cudaGetSymbolAddress((void**)&acth,    g_act_h);
    cudaGetSymbolAddress((void**)&actl,    g_act_l);
    cudaGetSymbolAddress((void**)&Gh,      g_Gh);
    cudaGetSymbolAddress((void**)&Gl,      g_Gl);
    cudaGetSymbolAddress((void**)&radialh, g_radial_h);

    cudaFuncSetAttribute(mma_gemm_ps<3,1,0>, cudaFuncAttributeMaxDynamicSharedMemorySize, 3*SSTAGE);
    cudaFuncSetAttribute(mma_gemm_ps<3,0,1>, cudaFuncAttributeMaxDynamicSharedMemorySize, 3*SSTAGE);

    const int TB = 256;
    zero_kernel<<<(N_NODES + TB - 1)/TB, TB>>>();
    hist_kernel<<<(N_EDGES + TB - 1)/TB, TB>>>(edst, batch);
    scan_kernel<<<1, 1024>>>();
    build_csr_kernel<<<(N_EDGES + TB - 1)/TB, TB>>>(edst);
    edge_geom_kernel<<<(N_EDGES + TB - 1)/TB, TB>>>(pos, shift, lattice, batch, esrc, edst);

    auto cvt = [&](const float* B, int off, int K, int Kcols, int stride, int dstOff) {
        int n = HDIM*Kcols;
        convertB_kernel<<<(n + TB - 1)/TB, TB>>>(B, bhi + off, blo + off, K, Kcols, stride, dstOff, HDIM);
    };
    const float inv_sqrt_deg = 0.28867513459481287f;  // 1/sqrt(12)

    cvt(W_embed, OFF_EMB, D_IN, 128, 128, 0);
    for (int l = 0; l < NLAYER; l++) {
        cvt(r2 + (size_t)l*RH*HDIM, OFF_R2 + l*32768, RH, 128, 128, 0);
        // Wcomb[l] = [ inv_sqrt_deg * Wtp@Wself  |  Wskip ]  as [256][2560]
        cvt(Wself + (size_t)l*HDIM*HDIM, OFF_WSELFT, HDIM, 256, 256, 0);
        dim3 gComb(2, KTP/128);
        mma_gemm<<<gComb, 256>>>(KTP, HDIM, 256, Wtp + (size_t)l*KTP*HDIM,
                                 bhi + OFF_WSELFT, blo + OFF_WSELFT,
                                 wtp2 + (size_t)l*KTP*HDIM, inv_sqrt_deg);
        cvt(wtp2 + (size_t)l*KTP*HDIM,   OFF_WCOMB + l*655360, KTP,  KTP, KPAD2, 0);
        cvt(Wskip + (size_t)l*HDIM*HDIM, OFF_WCOMB + l*655360, HDIM, 256, KPAD2, KTP);
    }

    // h = x @ W_embed
    dim3 gEmbed(2, (N_NODES + 127)/128);
    mma_gemm<<<gEmbed, 256>>>(N_NODES, D_IN, 128, x, bhi + OFF_EMB, blo + OFF_EMB, hA, 1.0f);
    splitH_kernel<<<(N_NODES*HDIM + TB - 1)/TB, TB>>>(hA);

    dim3 gNode(2, (N_NODES + 63)/64);   // (2, 313)
    dim3 gEdge(2, N_EDGES/64);          // (2, 3750)

    float* hc = hA;
    float* hn = hB;

    for (int l = 0; l < NLAYER; l++) {
        act_kernel<<<(N_EDGES + 7)/8, 256>>>(r1 + l*NB*RH, b1 + l*RH);
        // radial(fp16) = (act_h + act_l) @ r2[l], full 3-term split
        mma_gemm_ps<3,1,0><<<gEdge, 256, 3*SSTAGE>>>(N_EDGES, 128, acth, actl,
            bhi + OFF_R2 + l*32768, blo + OFF_R2 + l*32768, radialh, 1.0f);
        scatter_kernel<<<(N_NODES + 7)/8, 256>>>(hc, esrc);
        // hn = gelu( G @ Wtp' + h @ Wskip )  -- one fused GEMM over K=2560
        mma_gemm_ps<3,0,1><<<gNode, 256, 3*SSTAGE>>>(N_NODES, KPAD2, Gh, Gl,
            bhi + OFF_WCOMB + l*655360, blo + OFF_WCOMB + l*655360, hn, 1.0f);
        if (l + 1 < NLAYER)
            splitH_kernel<<<(N_NODES*HDIM + TB - 1)/TB, TB>>>(hn);
        float* t = hc; hc = hn; hn = t;
    }

    readout_kernel<<<(N_NODES + 7)/8, 256>>>(hc, Wout, batch);
    finalize_kernel<<<1, 256>>>(out);
}

// round 13
// speedup vs baseline: 3.1882x; 1.1626x over previous
#include <cuda_runtime.h>
#include <cuda_bf16.h>
#include <cuda_fp16.h>
#include <math.h>
#include <stdint.h>

#define N_NODES 20000
#define N_EDGES 240000
#define N_GRAPHS 200
#define D_IN 118
#define HDIM 256
#define NB 10
#define RH 100
#define NLAYER 3
#define SH9 9
#define KTP (SH9*HDIM)   // 2304
#define KPAD2 2560       // KTP + 256 (h tail for fused skip)

// ---------------- static device scratch (no allocation allowed) ----------------
__device__ float g_hA[N_NODES*HDIM];
__device__ float g_hB[N_NODES*HDIM];
__device__ float g_sh[N_EDGES*SH9];
__device__ float g_emb[N_EDGES*NB];
__device__ int   g_deg[N_NODES];
__device__ int   g_rowptr[N_NODES+1];
__device__ int   g_cursor[N_NODES];
__device__ int   g_csr[N_EDGES];
__device__ float g_sums[N_GRAPHS];
__device__ float g_cnts[N_GRAPHS];

__device__ __half g_radial_h[(size_t)N_EDGES*HDIM];   // 123 MB
__device__ __half g_act16[(size_t)N_EDGES*128];       // 61 MB
__device__ __half g_G16[(size_t)N_NODES*KPAD2];       // 102 MB
__device__ float  g_wtp2[NLAYER*KTP*HDIM];            // 7 MB

// fp16 hi/lo weights: r2t [256][128] per layer; Wcomb [256][2560] per layer
#define OFF16_R2    0            /* + l*32768 */
#define OFF16_WCOMB 98304        /* + l*655360 */
#define W16_TOTAL   2064384
__device__ __half g_w16h[W16_TOTAL];
__device__ __half g_w16l[W16_TOTAL];

// bf16 hi/lo transposed weights (embed + combine temp only)
#define OFF_EMB    0
#define OFF_WSELFT 32768
#define BT_TOTAL   98304
__device__ __nv_bfloat16 g_bhi[BT_TOTAL];
__device__ __nv_bfloat16 g_blo[BT_TOTAL];

// ---------------- small utility kernels ----------------
__global__ void zero_kernel() {
    int i = blockIdx.x*blockDim.x + threadIdx.x;
    if (i < N_NODES) g_deg[i] = 0;
    if (i < N_GRAPHS) { g_sums[i] = 0.0f; g_cnts[i] = 0.0f; }
}

__global__ void hist_kernel(const int* __restrict__ dst, const int* __restrict__ batch) {
    int i = blockIdx.x*blockDim.x + threadIdx.x;
    if (i < N_EDGES) atomicAdd(&g_deg[dst[i]], 1);
    if (i < N_NODES) atomicAdd(&g_cnts[batch[i]], 1.0f);
}

__global__ void scan_kernel() {
    __shared__ int s[1024];
    __shared__ int carry;
    int tid = threadIdx.x;
    if (tid == 0) carry = 0;
    __syncthreads();
    for (int base = 0; base < N_NODES; base += 1024) {
        int i = base + tid;
        int v = (i < N_NODES) ? g_deg[i] : 0;
        s[tid] = v;
        __syncthreads();
        for (int off = 1; off < 1024; off <<= 1) {
            int t = (tid >= off) ? s[tid-off] : 0;
            __syncthreads();
            if (tid >= off) s[tid] += t;
            __syncthreads();
        }
        int inc = s[tid] + carry;
        if (i < N_NODES) { g_rowptr[i+1] = inc; g_cursor[i] = inc - v; }
        if (i == 0) g_rowptr[0] = 0;
        __syncthreads();
        if (tid == 1023) carry = inc;
        __syncthreads();
    }
}

__global__ void build_csr_kernel(const int* __restrict__ dst) {
    int e = blockIdx.x*blockDim.x + threadIdx.x;
    if (e >= N_EDGES) return;
    int p = atomicAdd(&g_cursor[dst[e]], 1);
    g_csr[p] = e;
}

__global__ void edge_geom_kernel(const float* __restrict__ pos,
                                 const float* __restrict__ shift,
                                 const float* __restrict__ lattice,
                                 const int* __restrict__ batch,
                                 const int* __restrict__ src,
                                 const int* __restrict__ dst) {
    int e = blockIdx.x*blockDim.x + threadIdx.x;
    if (e >= N_EDGES) return;
    int s = src[e], d = dst[e];
    int b = batch[s];
    float sx = shift[e*3+0], sy = shift[e*3+1], sz = shift[e*3+2];
    const float* L = lattice + b*9;
    float v[3];
    #pragma unroll
    for (int j = 0; j < 3; j++)
        v[j] = pos[d*3+j] - pos[s*3+j] + sx*L[j] + sy*L[3+j] + sz*L[6+j];
    float len = sqrtf(v[0]*v[0] + v[1]*v[1] + v[2]*v[2]);
    float inv = 1.0f/(len + 1e-12f);
    float ux = v[0]*inv, uy = v[1]*inv, uz = v[2]*inv;
    const float c1 = 1.7320508075688772f;
    const float c2 = 3.872983346207417f;
    float* shp = g_sh + e*SH9;
    shp[0] = 1.0f;
    shp[1] = c1*ux;
    shp[2] = c1*uy;
    shp[3] = c1*uz;
    shp[4] = c2*ux*uy;
    shp[5] = c2*uy*uz;
    shp[6] = 1.118033988749895f*(3.0f*uz*uz - 1.0f);
    shp[7] = c2*ux*uz;
    shp[8] = 1.9364916731037085f*(ux*ux - uy*uy);
    const float step = 5.0f/11.0f;
    const float sq10 = 3.1622776601683795f;
    float* ep = g_emb + e*NB;
    #pragma unroll
    for (int i = 0; i < NB; i++) {
        float val = step*(float)(i+1);
        float diff = (len - val)/step;
        float em = 0.0f;
        if (diff > -1.0f && diff < 1.0f)
            em = cosf(1.5707963267948966f*diff)*sq10;
        ep[i] = em;
    }
}

// act = silu(emb @ r1 + b1), single fp16, K padded to 128
__global__ void act_kernel(const float* __restrict__ r1, const float* __restrict__ b1) {
    int w = (blockIdx.x*blockDim.x + threadIdx.x) >> 5;
    int lane = threadIdx.x & 31;
    if (w >= N_EDGES) return;
    float em[NB];
    const float* ep = g_emb + w*NB;
    #pragma unroll
    for (int i = 0; i < NB; i++) em[i] = ep[i];
    #pragma unroll
    for (int j = lane; j < 128; j += 32) {
        float val = 0.0f;
        if (j < RH) {
            float s = b1[j];
            #pragma unroll
            for (int i = 0; i < NB; i++) s += em[i]*r1[i*RH + j];
            val = s/(1.0f + expf(-s));
        }
        g_act16[(size_t)w*128 + j] = __float2half_rn(val);
    }
}

// scatter: G[n, a*256+k] = sum_{e: dst=n} sh[e,a]*h[src[e],k]*radial[e,k]  (cols 0..2303, stride KPAD2)
__global__ void __launch_bounds__(256) scatter_kernel(const float* __restrict__ h,
                                                      const int* __restrict__ src) {
    int n = blockIdx.x*8 + (threadIdx.x >> 5);
    int lane = threadIdx.x & 31;
    if (n >= N_NODES) return;
    float acc[SH9][4][2];
    #pragma unroll
    for (int a = 0; a < SH9; a++)
        #pragma unroll
        for (int j = 0; j < 4; j++) { acc[a][j][0] = 0.0f; acc[a][j][1] = 0.0f; }
    int beg = g_rowptr[n], end = g_rowptr[n+1];
    for (int idx = beg; idx < end; ++idx) {
        int e = g_csr[idx];
        int s = src[e];
        float shv[SH9];
        const float* sp = g_sh + e*SH9;
        #pragma unroll
        for (int a = 0; a < SH9; a++) shv[a] = sp[a];
        const float* hp = h + (size_t)s*HDIM;
        const __half* rp = g_radial_h + (size_t)e*HDIM;
        #pragma unroll
        for (int j = 0; j < 4; j++) {
            int k = j*64 + lane*2;
            float2 hv = *(const float2*)(hp + k);
            float2 rf = __half22float2(*(const __half2*)(rp + k));
            float hs0 = hv.x*rf.x;
            float hs1 = hv.y*rf.y;
            #pragma unroll
            for (int a = 0; a < SH9; a++) {
                acc[a][j][0] += shv[a]*hs0;
                acc[a][j][1] += shv[a]*hs1;
            }
        }
    }
    __half* gp = g_G16 + (size_t)n*KPAD2;
    #pragma unroll
    for (int a = 0; a < SH9; a++)
        #pragma unroll
        for (int j = 0; j < 4; j++) {
            int k = a*256 + j*64 + lane*2;
            *(__half2*)(gp + k) = __floats2half2_rn(acc[a][j][0], acc[a][j][1]);
        }
}

// write h (fp16) into G tail cols [KTP, KTP+256)
__global__ void storeH16_kernel(const float* __restrict__ h) {
    int i = blockIdx.x*blockDim.x + threadIdx.x;
    if (i >= N_NODES*HDIM) return;
    int n = i >> 8, k = i & 255;
    g_G16[(size_t)n*KPAD2 + KTP + k] = __float2half_rn(h[i]);
}

// ---------------- weight convert/transpose ----------------
// B[K][N] fp32 -> bf16 hi/lo dst[n*dstStride + dstOff + k]
__global__ void convertB_kernel(const float* __restrict__ B,
                                __nv_bfloat16* __restrict__ hi,
                                __nv_bfloat16* __restrict__ lo,
                                int K, int Kcols, int dstStride, int dstOff, int N) {
    int i = blockIdx.x*blockDim.x + threadIdx.x;
    if (i >= N*Kcols) return;
    int n = i / Kcols, k = i - n*Kcols;
    float v = (k < K) ? B[(size_t)k*N + n] : 0.0f;
    __nv_bfloat16 h = __float2bfloat16_rn(v);
    size_t di = (size_t)n*dstStride + dstOff + k;
    hi[di] = h;
    lo[di] = __float2bfloat16_rn(v - __bfloat162float(h));
}

// B[K][N] fp32 -> fp16 hi/lo dst[n*dstStride + dstOff + k]
__global__ void convertW16s_kernel(const float* __restrict__ B,
                                   __half* __restrict__ hi, __half* __restrict__ lo,
                                   int K, int Kcols, int dstStride, int dstOff, int N) {
    int i = blockIdx.x*blockDim.x + threadIdx.x;
    if (i >= N*Kcols) return;
    int n = i / Kcols, k = i - n*Kcols;
    float v = (k < K) ? B[(size_t)k*N + n] : 0.0f;
    __half h = __float2half_rn(v);
    size_t di = (size_t)n*dstStride + dstOff + k;
    hi[di] = h;
    lo[di] = __float2half_rn(v - __half2float(h));
}

// ---------------- MMA helpers ----------------
__device__ __forceinline__ void mma_bf16(float* c, const uint32_t* a, const uint32_t* b) {
    asm volatile(
        "mma.sync.aligned.m16n8k16.row.col.f32.bf16.bf16.f32 "
        "{%0,%1,%2,%3}, {%4,%5,%6,%7}, {%8,%9}, {%0,%1,%2,%3};\n"
        : "+f"(c[0]), "+f"(c[1]), "+f"(c[2]), "+f"(c[3])
        : "r"(a[0]), "r"(a[1]), "r"(a[2]), "r"(a[3]), "r"(b[0]), "r"(b[1]));
}

__device__ __forceinline__ void mma_f16(float* c, const uint32_t* a, const uint32_t* b) {
    asm volatile(
        "mma.sync.aligned.m16n8k16.row.col.f32.f16.f16.f32 "
        "{%0,%1,%2,%3}, {%4,%5,%6,%7}, {%8,%9}, {%0,%1,%2,%3};\n"
        : "+f"(c[0]), "+f"(c[1]), "+f"(c[2]), "+f"(c[3])
        : "r"(a[0]), "r"(a[1]), "r"(a[2]), "r"(a[3]), "r"(b[0]), "r"(b[1]));
}

__device__ __forceinline__ void ldsm_x4(uint32_t* r, uint32_t addr) {
    asm volatile("ldmatrix.sync.aligned.m8n8.x4.shared.b16 {%0,%1,%2,%3}, [%4];\n"
        : "=r"(r[0]), "=r"(r[1]), "=r"(r[2]), "=r"(r[3]) : "r"(addr));
}

__device__ __forceinline__ void cp16(uint32_t dst, const void* src) {
    asm volatile("cp.async.cg.shared.global [%0], [%1], 16;\n" :: "r"(dst), "l"(src));
}

__device__ __forceinline__ float gelu_f(float x) {
    float inner = 0.7978845608028654f*(x + 0.044715f*x*x*x);
    return 0.5f*x*(1.0f + tanhf(inner));
}

// ============ A-single / B-split fp16 pipelined GEMM: 64x128x32, 3-stage ============
// C[M,256] = actf(alpha * A[M,Kpad] @ (Bh+Bl)^T)
// A fp16 [M][Kpad] (data, single); Bh/Bl fp16 [256][Kpad] (weights, split -> exact)
#define LDSB 40
#define SSTGS 25600   // A 5120 | Bh 10240 | Bl 10240
template<int OUTHALF, int ACTG>
__global__ void __launch_bounds__(256, 2) mma_gemm_f16s(int M, int Kpad,
    const __half* __restrict__ A,
    const __half* __restrict__ Bh, const __half* __restrict__ Bl,
    void* __restrict__ Cout, float alpha)
{
    extern __shared__ char dsmem[];
    uint32_t smem_base = (uint32_t)__cvta_generic_to_shared(dsmem);

    int tid = threadIdx.x;
    int lane = tid & 31, warp = tid >> 5;
    int wm = (warp >> 2) * 32;
    int wn = (warp & 3) * 32;
    int bm = blockIdx.y * 64;
    int bn = blockIdx.x * 128;
    int nk = Kpad >> 5;

    float acc[2][4][4];
    #pragma unroll
    for (int i = 0; i < 2; i++)
        #pragma unroll
        for (int j = 0; j < 4; j++)
            #pragma unroll
            for (int r = 0; r < 4; r++) acc[i][j][r] = 0.0f;

    auto issue_load = [&](int ks) {
        uint32_t sb = smem_base + (ks % 3)*SSTGS;
        int k0 = ks*32;
        // A: 64 rows x 32 cols fp16, one 16B chunk per thread
        {
            int row = tid >> 2, koff = (tid & 3)*8;
            int ar = bm + row; if (ar > M-1) ar = M-1;
            cp16(sb + (uint32_t)(row*LDSB + koff)*2u, A + (size_t)ar*Kpad + k0 + koff);
        }
        // Bh/Bl: 128 rows x 32 cols fp16 each, two 16B chunks per thread each
        #pragma unroll
        for (int c2 = 0; c2 < 2; c2++) {
            int c = tid + c2*256;
            int row = c >> 2, koff = (c & 3)*8;
            size_t boff = (size_t)(bn + row)*Kpad + k0 + koff;
            uint32_t d = sb + 5120u + (uint32_t)(row*LDSB + koff)*2u;
            cp16(d, Bh + boff);
            cp16(d + 10240u, Bl + boff);
        }
        asm volatile("cp.async.commit_group;\n" ::);
    };

    issue_load(0);
    issue_load(1);

    for (int ks = 0; ks < nk; ks++) {
        asm volatile("cp.async.wait_group 1;\n" ::);
        __syncthreads();
        if (ks + 2 < nk) issue_load(ks + 2);
        uint32_t sb = smem_base + (ks % 3)*SSTGS;

        #pragma unroll
        for (int kt = 0; kt < 2; kt++) {
            int c0 = kt*16;
            uint32_t bfh[4][2], bfl[4][2];
            #pragma unroll
            for (int ntp = 0; ntp < 2; ntp++) {
                int brow = wn + ntp*16 + (lane & 7) + (lane >> 4)*8;
                int bcol = c0 + ((lane >> 3) & 1)*8;
                uint32_t off = (uint32_t)(brow*LDSB + bcol)*2u;
                uint32_t rh[4], rl[4];
                ldsm_x4(rh, sb + 5120u + off);
                ldsm_x4(rl, sb + 15360u + off);
                bfh[ntp*2+0][0] = rh[0]; bfh[ntp*2+0][1] = rh[1];
                bfh[ntp*2+1][0] = rh[2]; bfh[ntp*2+1][1] = rh[3];
                bfl[ntp*2+0][0] = rl[0]; bfl[ntp*2+0][1] = rl[1];
                bfl[ntp*2+1][0] = rl[2]; bfl[ntp*2+1][1] = rl[3];
            }
            int arow_l = (lane & 7) + ((lane >> 3) & 1)*8;
            int acol_l = c0 + (lane >> 4)*8;
            #pragma unroll
            for (int mt = 0; mt < 2; mt++) {
                uint32_t af[4];
                ldsm_x4(af, sb + (uint32_t)((wm + mt*16 + arow_l)*LDSB + acol_l)*2u);
                #pragma unroll
                for (int nt = 0; nt < 4; nt++) {
                    mma_f16(acc[mt][nt], af, bfh[nt]);
                    mma_f16(acc[mt][nt], af, bfl[nt]);
                }
            }
        }
        __syncthreads();
    }

    #pragma unroll
    for (int mt = 0; mt < 2; mt++) {
        int rbase = bm + wm + mt*16 + (lane >> 2);
        #pragma unroll
        for (int half = 0; half < 2; half++) {
            int rr = rbase + half*8;
            if (rr < M) {
                #pragma unroll
                for (int nt = 0; nt < 4; nt++) {
                    int cc = bn + wn + nt*8 + 2*(lane & 3);
                    float v0 = alpha*acc[mt][nt][half*2 + 0];
                    float v1 = alpha*acc[mt][nt][half*2 + 1];
                    if (ACTG) { v0 = gelu_f(v0); v1 = gelu_f(v1); }
                    if (OUTHALF) {
                        *(__half2*)((__half*)Cout + (size_t)rr*HDIM + cc) = __floats2half2_rn(v0, v1);
                    } else {
                        *(float2*)((float*)Cout + (size_t)rr*HDIM + cc) = make_float2(v0, v1);
                    }
                }
            }
        }
    }
}

// ============ fp32-A 3-term bf16 GEMM (embed + weight-combine; accuracy-critical) ============
__global__ void __launch_bounds__(256, 1) mma_gemm(int M, int K, int Kpad,
    const float* __restrict__ A,
    const __nv_bfloat16* __restrict__ Bth,
    const __nv_bfloat16* __restrict__ Btl,
    float* __restrict__ C, float alpha)
{
    constexpr int N = 256;
    __shared__ uint16_t As_h[128*LDSB];
    __shared__ uint16_t As_l[128*LDSB];
    __shared__ uint16_t Bs_h[128*LDSB];
    __shared__ uint16_t Bs_l[128*LDSB];

    int tid = threadIdx.x;
    int lane = tid & 31, warp = tid >> 5;
    int wm = (warp >> 2) * 64;
    int wn = (warp & 3) * 32;
    int bm = blockIdx.y * 128;
    int bn = blockIdx.x * 128;

    float acc[4][4][4];
    #pragma unroll
    for (int i = 0; i < 4; i++)
        #pragma unroll
        for (int j = 0; j < 4; j++)
            #pragma unroll
            for (int r = 0; r < 4; r++) acc[i][j][r] = 0.0f;

    const int arow = tid >> 1, acb = (tid & 1) * 16;
    const int gm = bm + arow;
    const bool aok = gm < M;
    const bool kdiv4 = (K & 3) == 0;
    const int brow = tid >> 1, bcb = (tid & 1) * 16;

    float4 av[4];
    uint4 bhv[2], blv[2];

    auto fetchA = [&](int k0) {
        if (aok && kdiv4 && (k0 + acb + 16 <= K)) {
            const float* p = A + (size_t)gm*K + k0 + acb;
            av[0] = *(const float4*)(p);
            av[1] = *(const float4*)(p + 4);
            av[2] = *(const float4*)(p + 8);
            av[3] = *(const float4*)(p + 12);
        } else {
            const float* p = A + (size_t)gm*K;
            #pragma unroll
            for (int i = 0; i < 4; i++) {
                float t[4];
                #pragma unroll
                for (int j = 0; j < 4; j++) {
                    int kk = k0 + acb + i*4 + j;
                    t[j] = (aok && kk < K) ? p[kk] : 0.0f;
                }
                av[i] = make_float4(t[0], t[1], t[2], t[3]);
            }
        }
    };
    auto fetchB = [&](int k0) {
        const __nv_bfloat16* ph = Bth + (size_t)(bn + brow)*Kpad + k0 + bcb;
        const __nv_bfloat16* pl = Btl + (size_t)(bn + brow)*Kpad + k0 + bcb;
        bhv[0] = *(const uint4*)(ph);
        bhv[1] = *(const uint4*)(ph + 8);
        blv[0] = *(const uint4*)(pl);
        blv[1] = *(const uint4*)(pl + 8);
    };
    auto stage = [&]() {
        uint16_t* da = &As_h[arow*LDSB + acb];
        uint16_t* dal = &As_l[arow*LDSB + acb];
        #pragma unroll
        for (int i = 0; i < 4; i++) {
            float4 v = av[i];
            __nv_bfloat162 h01 = __floats2bfloat162_rn(v.x, v.y);
            __nv_bfloat162 h23 = __floats2bfloat162_rn(v.z, v.w);
            __nv_bfloat162 l01 = __floats2bfloat162_rn(v.x - __bfloat162float(h01.x),
                                                       v.y - __bfloat162float(h01.y));
            __nv_bfloat162 l23 = __floats2bfloat162_rn(v.z - __bfloat162float(h23.x),
                                                       v.w - __bfloat162float(h23.y));
            *(uint32_t*)(da + i*4)     = *(uint32_t*)&h01;
            *(uint32_t*)(da + i*4 + 2) = *(uint32_t*)&h23;
            *(uint32_t*)(dal + i*4)     = *(uint32_t*)&l01;
            *(uint32_t*)(dal + i*4 + 2) = *(uint32_t*)&l23;
        }
        uint16_t* db = &Bs_h[brow*LDSB + bcb];
        uint16_t* dbl = &Bs_l[brow*LDSB + bcb];
        *(uint2*)(db)      = make_uint2(bhv[0].x, bhv[0].y);
        *(uint2*)(db + 4)  = make_uint2(bhv[0].z, bhv[0].w);
        *(uint2*)(db + 8)  = make_uint2(bhv[1].x, bhv[1].y);
        *(uint2*)(db + 12) = make_uint2(bhv[1].z, bhv[1].w);
        *(uint2*)(dbl)      = make_uint2(blv[0].x, blv[0].y);
        *(uint2*)(dbl + 4)  = make_uint2(blv[0].z, blv[0].w);
        *(uint2*)(dbl + 8)  = make_uint2(blv[1].x, blv[1].y);
        *(uint2*)(dbl + 12) = make_uint2(blv[1].z, blv[1].w);
    };

    fetchA(0); fetchB(0);
    for (int k0 = 0; k0 < Kpad; k0 += 32) {
        stage();
        __syncthreads();
        if (k0 + 32 < Kpad) { fetchA(k0 + 32); fetchB(k0 + 32); }
        #pragma unroll
        for (int kt = 0; kt < 2; kt++) {
            int c = kt*16 + 2*(lane & 3);
            int r0 = lane >> 2;
            uint32_t bh[4][2], bl[4][2];
            #pragma unroll
            for (int nt = 0; nt < 4; nt++) {
                const uint16_t* pb  = &Bs_h[(wn + nt*8 + r0)*LDSB + c];
                const uint16_t* pbl = &Bs_l[(wn + nt*8 + r0)*LDSB + c];
                bh[nt][0] = *(const uint32_t*)(pb);
                bh[nt][1] = *(const uint32_t*)(pb + 8);
                bl[nt][0] = *(const uint32_t*)(pbl);
                bl[nt][1] = *(const uint32_t*)(pbl + 8);
            }
            #pragma unroll
            for (int mt = 0; mt < 4; mt++) {
                const uint16_t* pa  = &As_h[(wm + mt*16 + r0)*LDSB + c];
                const uint16_t* pal = &As_l[(wm + mt*16 + r0)*LDSB + c];
                uint32_t ah[4], al[4];
                ah[0] = *(const uint32_t*)(pa);
                ah[1] = *(const uint32_t*)(pa + 8*LDSB);
                ah[2] = *(const uint32_t*)(pa + 8);
                ah[3] = *(const uint32_t*)(pa + 8*LDSB + 8);
                al[0] = *(const uint32_t*)(pal);
                al[1] = *(const uint32_t*)(pal + 8*LDSB);
                al[2] = *(const uint32_t*)(pal + 8);
                al[3] = *(const uint32_t*)(pal + 8*LDSB + 8);
                #pragma unroll
                for (int nt = 0; nt < 4; nt++) {
                    mma_bf16(acc[mt][nt], ah, bh[nt]);
                    mma_bf16(acc[mt][nt], ah, bl[nt]);
                    mma_bf16(acc[mt][nt], al, bh[nt]);
                }
            }
        }
        __syncthreads();
    }

    #pragma unroll
    for (int mt = 0; mt < 4; mt++) {
        int rbase = bm + wm + mt*16 + (lane >> 2);
        #pragma unroll
        for (int half = 0; half < 2; half++) {
            int rr = rbase + half*8;
            if (rr < M) {
                #pragma unroll
                for (int nt = 0; nt < 4; nt++) {
                    int cc = bn + wn + nt*8 + 2*(lane & 3);
                    float v0 = alpha*acc[mt][nt][half*2 + 0];
                    float v1 = alpha*acc[mt][nt][half*2 + 1];
                    *(float2*)(C + (size_t)rr*N + cc) = make_float2(v0, v1);
                }
            }
        }
    }
}

// readout: node_out = h @ Wout, segment-sum by graph
__global__ void readout_kernel(const float* __restrict__ h,
                               const float* __restrict__ Wout,
                               const int* __restrict__ batch) {
    int n = blockIdx.x*8 + (threadIdx.x >> 5);
    int lane = threadIdx.x & 31;
    if (n >= N_NODES) return;
    float s = 0.0f;
    #pragma unroll
    for (int k = 0; k < 8; k++)
        s += h[(size_t)n*HDIM + k*32 + lane]*Wout[k*32 + lane];
    #pragma unroll
    for (int o = 16; o > 0; o >>= 1) s += __shfl_xor_sync(0xffffffffu, s, o);
    if (lane == 0) atomicAdd(&g_sums[batch[n]], s);
}

__global__ void finalize_kernel(float* __restrict__ out) {
    int g = threadIdx.x;
    if (g < N_GRAPHS) out[g] = g_sums[g]/fmaxf(g_cnts[g], 1.0f);
}

// ---------------- launch ----------------
extern "C" void kernel_launch(void* const* d_in, const int* in_sizes, int n_in,
                              void* d_out, int out_size) {
    (void)in_sizes; (void)n_in; (void)out_size;
    const float* x       = (const float*)d_in[0];
    const float* pos     = (const float*)d_in[1];
    const float* shift   = (const float*)d_in[2];
    const float* lattice = (const float*)d_in[3];
    const float* W_embed = (const float*)d_in[4];
    const float* r1      = (const float*)d_in[5];
    const float* b1      = (const float*)d_in[6];
    const float* r2      = (const float*)d_in[7];
    const float* Wtp     = (const float*)d_in[8];
    const float* Wself   = (const float*)d_in[9];
    const float* Wskip   = (const float*)d_in[10];
    const float* Wout    = (const float*)d_in[11];
    const int*   eidx    = (const int*)d_in[12];
    const int*   batch   = (const int*)d_in[13];
    const int* esrc = eidx;
    const int* edst = eidx + N_EDGES;
    float* out = (float*)d_out;

    float *hA, *hB, *wtp2;
    __nv_bfloat16 *bhi, *blo;
    __half *w16h, *w16l, *act16, *G16, *radialh;
    cudaGetSymbolAddress((void**)&hA,      g_hA);
    cudaGetSymbolAddress((void**)&hB,      g_hB);
    cudaGetSymbolAddress((void**)&wtp2,    g_wtp2);
    cudaGetSymbolAddress((void**)&bhi,     g_bhi);
    cudaGetSymbolAddress((void**)&blo,     g_blo);
    cudaGetSymbolAddress((void**)&w16h,    g_w16h);
    cudaGetSymbolAddress((void**)&w16l,    g_w16l);
    cudaGetSymbolAddress((void**)&act16,   g_act16);
    cudaGetSymbolAddress((void**)&G16,     g_G16);
    cudaGetSymbolAddress((void**)&radialh, g_radial_h);

    cudaFuncSetAttribute(mma_gemm_f16s<1,0>, cudaFuncAttributeMaxDynamicSharedMemorySize, 3*SSTGS);
    cudaFuncSetAttribute(mma_gemm_f16s<0,1>, cudaFuncAttributeMaxDynamicSharedMemorySize, 3*SSTGS);

    const int TB = 256;
    zero_kernel<<<(N_NODES + TB - 1)/TB, TB>>>();
    hist_kernel<<<(N_EDGES + TB - 1)/TB, TB>>>(edst, batch);
    scan_kernel<<<1, 1024>>>();
    build_csr_kernel<<<(N_EDGES + TB - 1)/TB, TB>>>(edst);
    edge_geom_kernel<<<(N_EDGES + TB - 1)/TB, TB>>>(pos, shift, lattice, batch, esrc, edst);

    const float inv_sqrt_deg = 0.28867513459481287f;  // 1/sqrt(12)

    // embed weights: bf16 hi/lo (accuracy path)
    convertB_kernel<<<(HDIM*128 + TB - 1)/TB, TB>>>(W_embed, bhi + OFF_EMB, blo + OFF_EMB,
                                                    D_IN, 128, 128, 0, HDIM);
    for (int l = 0; l < NLAYER; l++) {
        // r2 -> fp16 hi/lo [256][128]
        convertW16s_kernel<<<(HDIM*128 + TB - 1)/TB, TB>>>(r2 + (size_t)l*RH*HDIM,
            w16h + OFF16_R2 + l*32768, w16l + OFF16_R2 + l*32768, RH, 128, 128, 0, HDIM);
        // Wcomb[l] = [ inv_sqrt_deg * Wtp@Wself | Wskip ] -> fp16 hi/lo [256][2560]
        convertB_kernel<<<(HDIM*256 + TB - 1)/TB, TB>>>(Wself + (size_t)l*HDIM*HDIM,
            bhi + OFF_WSELFT, blo + OFF_WSELFT, HDIM, 256, 256, 0, HDIM);
        dim3 gComb(2, KTP/128);
        mma_gemm<<<gComb, 256>>>(KTP, HDIM, 256, Wtp + (size_t)l*KTP*HDIM,
                                 bhi + OFF_WSELFT, blo + OFF_WSELFT,
                                 wtp2 + (size_t)l*KTP*HDIM, inv_sqrt_deg);
        convertW16s_kernel<<<(HDIM*KTP + TB - 1)/TB, TB>>>(wtp2 + (size_t)l*KTP*HDIM,
            w16h + OFF16_WCOMB + l*655360, w16l + OFF16_WCOMB + l*655360,
            KTP, KTP, KPAD2, 0, HDIM);
        convertW16s_kernel<<<(HDIM*256 + TB - 1)/TB, TB>>>(Wskip + (size_t)l*HDIM*HDIM,
            w16h + OFF16_WCOMB + l*655360, w16l + OFF16_WCOMB + l*655360,
            HDIM, 256, KPAD2, KTP, HDIM);
    }

    // h = x @ W_embed  (fp32-A bf16-split path for accuracy)
    dim3 gEmbed(2, (N_NODES + 127)/128);
    mma_gemm<<<gEmbed, 256>>>(N_NODES, D_IN, 128, x, bhi + OFF_EMB, blo + OFF_EMB, hA, 1.0f);
    storeH16_kernel<<<(N_NODES*HDIM + TB - 1)/TB, TB>>>(hA);

    dim3 gNode(2, (N_NODES + 63)/64);   // (2, 313)
    dim3 gEdge(2, N_EDGES/64);          // (2, 3750)

    float* hc = hA;
    float* hn = hB;

    for (int l = 0; l < NLAYER; l++) {
        act_kernel<<<(N_EDGES + 7)/8, 256>>>(r1 + l*NB*RH, b1 + l*RH);
        // radial(fp16) = act(fp16, single) @ (r2h + r2l), 2 terms
        mma_gemm_f16s<1,0><<<gEdge, 256, 3*SSTGS>>>(N_EDGES, 128, act16,
            w16h + OFF16_R2 + l*32768, w16l + OFF16_R2 + l*32768, radialh, 1.0f);
        scatter_kernel<<<(N_NODES + 7)/8, 256>>>(hc, esrc);
        // hn = gelu( G @ Wtp' + h @ Wskip ), G single fp16, weights split, 2 terms
        mma_gemm_f16s<0,1><<<gNode, 256, 3*SSTGS>>>(N_NODES, KPAD2, G16,
            w16h + OFF16_WCOMB + l*655360, w16l + OFF16_WCOMB + l*655360, hn, 1.0f);
        if (l + 1 < NLAYER)
            storeH16_kernel<<<(N_NODES*HDIM + TB - 1)/TB, TB>>>(hn);
        float* t = hc; hc = hn; hn = t;
    }

    readout_kernel<<<(N_NODES + 7)/8, 256>>>(hc, Wout, batch);
    finalize_kernel<<<1, 256>>>(out);
}

// round 17
// speedup vs baseline: 4.2047x; 1.3188x over previous
#include <cuda_runtime.h>
#include <cuda_bf16.h>
#include <cuda_fp16.h>
#include <math.h>
#include <stdint.h>

#define N_NODES 20000
#define N_EDGES 240000
#define N_GRAPHS 200
#define D_IN 118
#define HDIM 256
#define NB 10
#define RH 100
#define NLAYER 3
#define SH9 9
#define KTP (SH9*HDIM)   // 2304
#define KPAD2 2560       // KTP + 256 (h tail for fused skip)
#define NBINS 4224       // multiple of 11 (kink-aligned) and 8 (block tiling)

// ---------------- static device scratch (no allocation allowed) ----------------
__device__ float g_hA[N_NODES*HDIM];
__device__ float g_hB[N_NODES*HDIM];
__device__ float g_sh[N_EDGES*SH9];
__device__ float g_len[N_EDGES];
__device__ int   g_deg[N_NODES];
__device__ int   g_rowptr[N_NODES+1];
__device__ int   g_cursor[N_NODES];
__device__ int   g_csr[N_EDGES];
__device__ float g_sums[N_GRAPHS];
__device__ float g_cnts[N_GRAPHS];

__device__ float  g_rtab[(size_t)(NBINS+1)*HDIM];     // 4.3 MB radial lookup table
__device__ __half g_G16h[(size_t)N_NODES*KPAD2];      // 102 MB
__device__ __half g_G16l[(size_t)N_NODES*KPAD2];      // tail cols only used
__device__ float  g_wtp2[NLAYER*KTP*HDIM];            // 7 MB

// fp16 hi/lo combined weights: Wcomb [256][2560] per layer
#define W16_TOTAL (NLAYER*HDIM*KPAD2)
__device__ __half g_w16h[W16_TOTAL];
__device__ __half g_w16l[W16_TOTAL];

// bf16 hi/lo transposed weights (embed + combine temp only)
#define OFF_EMB    0
#define OFF_WSELFT 32768
#define BT_TOTAL   98304
__device__ __nv_bfloat16 g_bhi[BT_TOTAL];
__device__ __nv_bfloat16 g_blo[BT_TOTAL];

// ---------------- small utility kernels ----------------
__global__ void zero_kernel() {
    int i = blockIdx.x*blockDim.x + threadIdx.x;
    if (i < N_NODES) g_deg[i] = 0;
    if (i < N_GRAPHS) { g_sums[i] = 0.0f; g_cnts[i] = 0.0f; }
}

__global__ void hist_kernel(const int* __restrict__ dst, const int* __restrict__ batch) {
    int i = blockIdx.x*blockDim.x + threadIdx.x;
    if (i < N_EDGES) atomicAdd(&g_deg[dst[i]], 1);
    if (i < N_NODES) atomicAdd(&g_cnts[batch[i]], 1.0f);
}

__global__ void scan_kernel() {
    __shared__ int s[1024];
    __shared__ int carry;
    int tid = threadIdx.x;
    if (tid == 0) carry = 0;
    __syncthreads();
    for (int base = 0; base < N_NODES; base += 1024) {
        int i = base + tid;
        int v = (i < N_NODES) ? g_deg[i] : 0;
        s[tid] = v;
        __syncthreads();
        for (int off = 1; off < 1024; off <<= 1) {
            int t = (tid >= off) ? s[tid-off] : 0;
            __syncthreads();
            if (tid >= off) s[tid] += t;
            __syncthreads();
        }
        int inc = s[tid] + carry;
        if (i < N_NODES) { g_rowptr[i+1] = inc; g_cursor[i] = inc - v; }
        if (i == 0) g_rowptr[0] = 0;
        __syncthreads();
        if (tid == 1023) carry = inc;
        __syncthreads();
    }
}

__global__ void build_csr_kernel(const int* __restrict__ dst) {
    int e = blockIdx.x*blockDim.x + threadIdx.x;
    if (e >= N_EDGES) return;
    int p = atomicAdd(&g_cursor[dst[e]], 1);
    g_csr[p] = e;
}

__global__ void edge_geom_kernel(const float* __restrict__ pos,
                                 const float* __restrict__ shift,
                                 const float* __restrict__ lattice,
                                 const int* __restrict__ batch,
                                 const int* __restrict__ src,
                                 const int* __restrict__ dst) {
    int e = blockIdx.x*blockDim.x + threadIdx.x;
    if (e >= N_EDGES) return;
    int s = src[e], d = dst[e];
    int b = batch[s];
    float sx = shift[e*3+0], sy = shift[e*3+1], sz = shift[e*3+2];
    const float* L = lattice + b*9;
    float v[3];
    #pragma unroll
    for (int j = 0; j < 3; j++)
        v[j] = pos[d*3+j] - pos[s*3+j] + sx*L[j] + sy*L[3+j] + sz*L[6+j];
    float len = sqrtf(v[0]*v[0] + v[1]*v[1] + v[2]*v[2]);
    float inv = 1.0f/(len + 1e-12f);
    float ux = v[0]*inv, uy = v[1]*inv, uz = v[2]*inv;
    const float c1 = 1.7320508075688772f;
    const float c2 = 3.872983346207417f;
    float* shp = g_sh + e*SH9;
    shp[0] = 1.0f;
    shp[1] = c1*ux;
    shp[2] = c1*uy;
    shp[3] = c1*uz;
    shp[4] = c2*ux*uy;
    shp[5] = c2*uy*uz;
    shp[6] = 1.118033988749895f*(3.0f*uz*uz - 1.0f);
    shp[7] = c2*ux*uz;
    shp[8] = 1.9364916731037085f*(ux*ux - uy*uy);
    g_len[e] = len;
}

// build radial table: T[bin][k] = (silu(emb(len_bin) @ r1 + b1) @ r2)[k], fp32.
// 8 bins per block; 256 threads (one output column each).
__global__ void rtab_kernel(const float* __restrict__ r1, const float* __restrict__ b1,
                            const float* __restrict__ r2) {
    __shared__ float sact[8][RH];
    int tid = threadIdx.x;
    int b0 = blockIdx.x*8;
    const float step = 5.0f/11.0f;
    const float sq10 = 3.1622776601683795f;
    for (int job = tid; job < 8*RH; job += 256) {
        int bb = job/RH, j = job - bb*RH;
        float len = (float)(b0 + bb)*(5.0f/(float)NBINS);
        float s = b1[j];
        #pragma unroll
        for (int i = 0; i < NB; i++) {
            float val = step*(float)(i+1);
            float diff = (len - val)/step;
            float em = 0.0f;
            if (diff > -1.0f && diff < 1.0f)
                em = cosf(1.5707963267948966f*diff)*sq10;
            s += em*r1[i*RH + j];
        }
        sact[bb][j] = s/(1.0f + expf(-s));
    }
    __syncthreads();
    float acc[8];
    #pragma unroll
    for (int bb = 0; bb < 8; bb++) acc[bb] = 0.0f;
    for (int j = 0; j < RH; j++) {
        float w = r2[j*HDIM + tid];
        #pragma unroll
        for (int bb = 0; bb < 8; bb++) acc[bb] += sact[bb][j]*w;
    }
    #pragma unroll
    for (int bb = 0; bb < 8; bb++) {
        int bin = b0 + bb;
        if (bin <= NBINS) g_rtab[(size_t)bin*HDIM + tid] = acc[bb];
    }
}

// scatter: G[n, a*256+k] = sum_{e: dst=n} sh[e,a]*h[src[e],k]*radial(len[e])[k]
// radial via fp32 table lerp (L2-resident). G written single fp16, cols 0..2303.
__global__ void __launch_bounds__(256) scatter_kernel(const float* __restrict__ h,
                                                      const int* __restrict__ src) {
    int n = blockIdx.x*8 + (threadIdx.x >> 5);
    int lane = threadIdx.x & 31;
    if (n >= N_NODES) return;
    float acc[SH9][4][2];
    #pragma unroll
    for (int a = 0; a < SH9; a++)
        #pragma unroll
        for (int j = 0; j < 4; j++) { acc[a][j][0] = 0.0f; acc[a][j][1] = 0.0f; }
    int beg = g_rowptr[n], end = g_rowptr[n+1];
    for (int idx = beg; idx < end; ++idx) {
        int e = g_csr[idx];
        int s = src[e];
        float shv[SH9];
        const float* sp = g_sh + e*SH9;
        #pragma unroll
        for (int a = 0; a < SH9; a++) shv[a] = sp[a];
        float ti = g_len[e]*((float)NBINS/5.0f);
        int i0 = (int)ti;
        if (i0 > NBINS-1) i0 = NBINS-1;
        float f = ti - (float)i0;
        if (f > 1.0f) f = 1.0f;
        const float* T0 = g_rtab + (size_t)i0*HDIM;
        const float* hp = h + (size_t)s*HDIM;
        #pragma unroll
        for (int j = 0; j < 4; j++) {
            int k = j*64 + lane*2;
            float2 hv = *(const float2*)(hp + k);
            float2 t0 = *(const float2*)(T0 + k);
            float2 t1 = *(const float2*)(T0 + HDIM + k);
            float r0 = t0.x + f*(t1.x - t0.x);
            float r1v = t0.y + f*(t1.y - t0.y);
            float hs0 = hv.x*r0;
            float hs1 = hv.y*r1v;
            #pragma unroll
            for (int a = 0; a < SH9; a++) {
                acc[a][j][0] += shv[a]*hs0;
                acc[a][j][1] += shv[a]*hs1;
            }
        }
    }
    __half* gp = g_G16h + (size_t)n*KPAD2;
    #pragma unroll
    for (int a = 0; a < SH9; a++)
        #pragma unroll
        for (int j = 0; j < 4; j++) {
            int k = a*256 + j*64 + lane*2;
            *(__half2*)(gp + k) = __floats2half2_rn(acc[a][j][0], acc[a][j][1]);
        }
}

// write h (fp16 hi/lo) into G tail cols [KTP, KTP+256)
__global__ void storeH16_kernel(const float* __restrict__ h) {
    int i = blockIdx.x*blockDim.x + threadIdx.x;
    if (i >= N_NODES*HDIM) return;
    int n = i >> 8, k = i & 255;
    float v = h[i];
    __half hi = __float2half_rn(v);
    g_G16h[(size_t)n*KPAD2 + KTP + k] = hi;
    g_G16l[(size_t)n*KPAD2 + KTP + k] = __float2half_rn(v - __half2float(hi));
}

// ---------------- weight convert/transpose ----------------
__global__ void convertB_kernel(const float* __restrict__ B,
                                __nv_bfloat16* __restrict__ hi,
                                __nv_bfloat16* __restrict__ lo,
                                int K, int Kcols, int dstStride, int dstOff, int N) {
    int i = blockIdx.x*blockDim.x + threadIdx.x;
    if (i >= N*Kcols) return;
    int n = i / Kcols, k = i - n*Kcols;
    float v = (k < K) ? B[(size_t)k*N + n] : 0.0f;
    __nv_bfloat16 h = __float2bfloat16_rn(v);
    size_t di = (size_t)n*dstStride + dstOff + k;
    hi[di] = h;
    lo[di] = __float2bfloat16_rn(v - __bfloat162float(h));
}

__global__ void convertW16s_kernel(const float* __restrict__ B,
                                   __half* __restrict__ hi, __half* __restrict__ lo,
                                   int K, int Kcols, int dstStride, int dstOff, int N) {
    int i = blockIdx.x*blockDim.x + threadIdx.x;
    if (i >= N*Kcols) return;
    int n = i / Kcols, k = i - n*Kcols;
    float v = (k < K) ? B[(size_t)k*N + n] : 0.0f;
    __half h = __float2half_rn(v);
    size_t di = (size_t)n*dstStride + dstOff + k;
    hi[di] = h;
    lo[di] = __float2half_rn(v - __half2float(h));
}

// ---------------- MMA helpers ----------------
__device__ __forceinline__ void mma_bf16(float* c, const uint32_t* a, const uint32_t* b) {
    asm volatile(
        "mma.sync.aligned.m16n8k16.row.col.f32.bf16.bf16.f32 "
        "{%0,%1,%2,%3}, {%4,%5,%6,%7}, {%8,%9}, {%0,%1,%2,%3};\n"
        : "+f"(c[0]), "+f"(c[1]), "+f"(c[2]), "+f"(c[3])
        : "r"(a[0]), "r"(a[1]), "r"(a[2]), "r"(a[3]), "r"(b[0]), "r"(b[1]));
}

__device__ __forceinline__ void mma_f16(float* c, const uint32_t* a, const uint32_t* b) {
    asm volatile(
        "mma.sync.aligned.m16n8k16.row.col.f32.f16.f16.f32 "
        "{%0,%1,%2,%3}, {%4,%5,%6,%7}, {%8,%9}, {%0,%1,%2,%3};\n"
        : "+f"(c[0]), "+f"(c[1]), "+f"(c[2]), "+f"(c[3])
        : "r"(a[0]), "r"(a[1]), "r"(a[2]), "r"(a[3]), "r"(b[0]), "r"(b[1]));
}

__device__ __forceinline__ void ldsm_x4(uint32_t* r, uint32_t addr) {
    asm volatile("ldmatrix.sync.aligned.m8n8.x4.shared.b16 {%0,%1,%2,%3}, [%4];\n"
        : "=r"(r[0]), "=r"(r[1]), "=r"(r[2]), "=r"(r[3]) : "r"(addr));
}

__device__ __forceinline__ void cp16(uint32_t dst, const void* src) {
    asm volatile("cp.async.cg.shared.global [%0], [%1], 16;\n" :: "r"(dst), "l"(src));
}

__device__ __forceinline__ float gelu_f(float x) {
    float inner = 0.7978845608028654f*(x + 0.044715f*x*x*x);
    return 0.5f*x*(1.0f + tanhf(inner));
}

// ============ node GEMM: hn = gelu( (A[+Al tail])@ (Bh+Bl)^T ) ============
// A fp16 [M][Kpad] single (G); Al fp16 hi/lo residual used ONLY for chunks k0>=Ksplit
// (the exact h tail). B fp16 [256][Kpad] hi/lo split (weights exact).
// 64x128x32 tiles, 3-stage cp.async.
#define LDSB 40
#define SSTGN 30720   // A 5120 | Bh 10240 | Bl 10240 | Al 5120
__global__ void __launch_bounds__(256, 2) mma_gemm_node(int M, int Kpad, int Ksplit,
    const __half* __restrict__ A, const __half* __restrict__ Al,
    const __half* __restrict__ Bh, const __half* __restrict__ Bl,
    float* __restrict__ Cout)
{
    extern __shared__ char dsmem[];
    uint32_t smem_base = (uint32_t)__cvta_generic_to_shared(dsmem);

    int tid = threadIdx.x;
    int lane = tid & 31, warp = tid >> 5;
    int wm = (warp >> 2) * 32;
    int wn = (warp & 3) * 32;
    int bm = blockIdx.y * 64;
    int bn = blockIdx.x * 128;
    int nk = Kpad >> 5;

    float acc[2][4][4];
    #pragma unroll
    for (int i = 0; i < 2; i++)
        #pragma unroll
        for (int j = 0; j < 4; j++)
            #pragma unroll
            for (int r = 0; r < 4; r++) acc[i][j][r] = 0.0f;

    auto issue_load = [&](int ks) {
        uint32_t sb = smem_base + (ks % 3)*SSTGN;
        int k0 = ks*32;
        {
            int row = tid >> 2, koff = (tid & 3)*8;
            int ar = bm + row; if (ar > M-1) ar = M-1;
            size_t ao = (size_t)ar*Kpad + k0 + koff;
            uint32_t da = sb + (uint32_t)(row*LDSB + koff)*2u;
            cp16(da, A + ao);
            if (k0 >= Ksplit) cp16(da + 25600u, Al + ao);
        }
        #pragma unroll
        for (int c2 = 0; c2 < 2; c2++) {
            int c = tid + c2*256;
            int row = c >> 2, koff = (c & 3)*8;
            size_t boff = (size_t)(bn + row)*Kpad + k0 + koff;
            uint32_t d = sb + 5120u + (uint32_t)(row*LDSB + koff)*2u;
            cp16(d, Bh + boff);
            cp16(d + 10240u, Bl + boff);
        }
        asm volatile("cp.async.commit_group;\n" ::);
    };

    issue_load(0);
    issue_load(1);

    for (int ks = 0; ks < nk; ks++) {
        asm volatile("cp.async.wait_group 1;\n" ::);
        __syncthreads();
        if (ks + 2 < nk) issue_load(ks + 2);
        uint32_t sb = smem_base + (ks % 3)*SSTGN;
        bool tail = (ks*32 >= Ksplit);

        #pragma unroll
        for (int kt = 0; kt < 2; kt++) {
            int c0 = kt*16;
            uint32_t bfh[4][2], bfl[4][2];
            #pragma unroll
            for (int ntp = 0; ntp < 2; ntp++) {
                int brow = wn + ntp*16 + (lane & 7) + (lane >> 4)*8;
                int bcol = c0 + ((lane >> 3) & 1)*8;
                uint32_t off = (uint32_t)(brow*LDSB + bcol)*2u;
                uint32_t rh[4], rl[4];
                ldsm_x4(rh, sb + 5120u + off);
                ldsm_x4(rl, sb + 15360u + off);
                bfh[ntp*2+0][0] = rh[0]; bfh[ntp*2+0][1] = rh[1];
                bfh[ntp*2+1][0] = rh[2]; bfh[ntp*2+1][1] = rh[3];
                bfl[ntp*2+0][0] = rl[0]; bfl[ntp*2+0][1] = rl[1];
                bfl[ntp*2+1][0] = rl[2]; bfl[ntp*2+1][1] = rl[3];
            }
            int arow_l = (lane & 7) + ((lane >> 3) & 1)*8;
            int acol_l = c0 + (lane >> 4)*8;
            #pragma unroll
            for (int mt = 0; mt < 2; mt++) {
                uint32_t aoff = (uint32_t)((wm + mt*16 + arow_l)*LDSB + acol_l)*2u;
                uint32_t af[4], afl[4];
                ldsm_x4(af, sb + aoff);
                if (tail) ldsm_x4(afl, sb + 25600u + aoff);
                #pragma unroll
                for (int nt = 0; nt < 4; nt++) {
                    mma_f16(acc[mt][nt], af, bfh[nt]);
                    mma_f16(acc[mt][nt], af, bfl[nt]);
                    if (tail) mma_f16(acc[mt][nt], afl, bfh[nt]);
                }
            }
        }
        __syncthreads();
    }

    #pragma unroll
    for (int mt = 0; mt < 2; mt++) {
        int rbase = bm + wm + mt*16 + (lane >> 2);
        #pragma unroll
        for (int half = 0; half < 2; half++) {
            int rr = rbase + half*8;
            if (rr < M) {
                #pragma unroll
                for (int nt = 0; nt < 4; nt++) {
                    int cc = bn + wn + nt*8 + 2*(lane & 3);
                    float v0 = gelu_f(acc[mt][nt][half*2 + 0]);
                    float v1 = gelu_f(acc[mt][nt][half*2 + 1]);
                    *(float2*)(Cout + (size_t)rr*HDIM + cc) = make_float2(v0, v1);
                }
            }
        }
    }
}

// ============ fp32-A 3-term bf16 GEMM (embed + weight-combine; accuracy-critical) ============
__global__ void __launch_bounds__(256, 1) mma_gemm(int M, int K, int Kpad,
    const float* __restrict__ A,
    const __nv_bfloat16* __restrict__ Bth,
    const __nv_bfloat16* __restrict__ Btl,
    float* __restrict__ C, float alpha)
{
    constexpr int N = 256;
    __shared__ uint16_t As_h[128*LDSB];
    __shared__ uint16_t As_l[128*LDSB];
    __shared__ uint16_t Bs_h[128*LDSB];
    __shared__ uint16_t Bs_l[128*LDSB];

    int tid = threadIdx.x;
    int lane = tid & 31, warp = tid >> 5;
    int wm = (warp >> 2) * 64;
    int wn = (warp & 3) * 32;
    int bm = blockIdx.y * 128;
    int bn = blockIdx.x * 128;

    float acc[4][4][4];
    #pragma unroll
    for (int i = 0; i < 4; i++)
        #pragma unroll
        for (int j = 0; j < 4; j++)
            #pragma unroll
            for (int r = 0; r < 4; r++) acc[i][j][r] = 0.0f;

    const int arow = tid >> 1, acb = (tid & 1) * 16;
    const int gm = bm + arow;
    const bool aok = gm < M;
    const bool kdiv4 = (K & 3) == 0;
    const int brow = tid >> 1, bcb = (tid & 1) * 16;

    float4 av[4];
    uint4 bhv[2], blv[2];

    auto fetchA = [&](int k0) {
        if (aok && kdiv4 && (k0 + acb + 16 <= K)) {
            const float* p = A + (size_t)gm*K + k0 + acb;
            av[0] = *(const float4*)(p);
            av[1] = *(const float4*)(p + 4);
            av[2] = *(const float4*)(p + 8);
            av[3] = *(const float4*)(p + 12);
        } else {
            const float* p = A + (size_t)gm*K;
            #pragma unroll
            for (int i = 0; i < 4; i++) {
                float t[4];
                #pragma unroll
                for (int j = 0; j < 4; j++) {
                    int kk = k0 + acb + i*4 + j;
                    t[j] = (aok && kk < K) ? p[kk] : 0.0f;
                }
                av[i] = make_float4(t[0], t[1], t[2], t[3]);
            }
        }
    };
    auto fetchB = [&](int k0) {
        const __nv_bfloat16* ph = Bth + (size_t)(bn + brow)*Kpad + k0 + bcb;
        const __nv_bfloat16* pl = Btl + (size_t)(bn + brow)*Kpad + k0 + bcb;
        bhv[0] = *(const uint4*)(ph);
        bhv[1] = *(const uint4*)(ph + 8);
        blv[0] = *(const uint4*)(pl);
        blv[1] = *(const uint4*)(pl + 8);
    };
    auto stage = [&]() {
        uint16_t* da = &As_h[arow*LDSB + acb];
        uint16_t* dal = &As_l[arow*LDSB + acb];
        #pragma unroll
        for (int i = 0; i < 4; i++) {
            float4 v = av[i];
            __nv_bfloat162 h01 = __floats2bfloat162_rn(v.x, v.y);
            __nv_bfloat162 h23 = __floats2bfloat162_rn(v.z, v.w);
            __nv_bfloat162 l01 = __floats2bfloat162_rn(v.x - __bfloat162float(h01.x),
                                                       v.y - __bfloat162float(h01.y));
            __nv_bfloat162 l23 = __floats2bfloat162_rn(v.z - __bfloat162float(h23.x),
                                                       v.w - __bfloat162float(h23.y));
            *(uint32_t*)(da + i*4)     = *(uint32_t*)&h01;
            *(uint32_t*)(da + i*4 + 2) = *(uint32_t*)&h23;
            *(uint32_t*)(dal + i*4)     = *(uint32_t*)&l01;
            *(uint32_t*)(dal + i*4 + 2) = *(uint32_t*)&l23;
        }
        uint16_t* db = &Bs_h[brow*LDSB + bcb];
        uint16_t* dbl = &Bs_l[brow*LDSB + bcb];
        *(uint2*)(db)      = make_uint2(bhv[0].x, bhv[0].y);
        *(uint2*)(db + 4)  = make_uint2(bhv[0].z, bhv[0].w);
        *(uint2*)(db + 8)  = make_uint2(bhv[1].x, bhv[1].y);
        *(uint2*)(db + 12) = make_uint2(bhv[1].z, bhv[1].w);
        *(uint2*)(dbl)      = make_uint2(blv[0].x, blv[0].y);
        *(uint2*)(dbl + 4)  = make_uint2(blv[0].z, blv[0].w);
        *(uint2*)(dbl + 8)  = make_uint2(blv[1].x, blv[1].y);
        *(uint2*)(dbl + 12) = make_uint2(blv[1].z, blv[1].w);
    };

    fetchA(0); fetchB(0);
    for (int k0 = 0; k0 < Kpad; k0 += 32) {
        stage();
        __syncthreads();
        if (k0 + 32 < Kpad) { fetchA(k0 + 32); fetchB(k0 + 32); }
        #pragma unroll
        for (int kt = 0; kt < 2; kt++) {
            int c = kt*16 + 2*(lane & 3);
            int r0 = lane >> 2;
            uint32_t bh[4][2], bl[4][2];
            #pragma unroll
            for (int nt = 0; nt < 4; nt++) {
                const uint16_t* pb  = &Bs_h[(wn + nt*8 + r0)*LDSB + c];
                const uint16_t* pbl = &Bs_l[(wn + nt*8 + r0)*LDSB + c];
                bh[nt][0] = *(const uint32_t*)(pb);
                bh[nt][1] = *(const uint32_t*)(pb + 8);
                bl[nt][0] = *(const uint32_t*)(pbl);
                bl[nt][1] = *(const uint32_t*)(pbl + 8);
            }
            #pragma unroll
            for (int mt = 0; mt < 4; mt++) {
                const uint16_t* pa  = &As_h[(wm + mt*16 + r0)*LDSB + c];
                const uint16_t* pal = &As_l[(wm + mt*16 + r0)*LDSB + c];
                uint32_t ah[4], al[4];
                ah[0] = *(const uint32_t*)(pa);
                ah[1] = *(const uint32_t*)(pa + 8*LDSB);
                ah[2] = *(const uint32_t*)(pa + 8);
                ah[3] = *(const uint32_t*)(pa + 8*LDSB + 8);
                al[0] = *(const uint32_t*)(pal);
                al[1] = *(const uint32_t*)(pal + 8*LDSB);
                al[2] = *(const uint32_t*)(pal + 8);
                al[3] = *(const uint32_t*)(pal + 8*LDSB + 8);
                #pragma unroll
                for (int nt = 0; nt < 4; nt++) {
                    mma_bf16(acc[mt][nt], ah, bh[nt]);
                    mma_bf16(acc[mt][nt], ah, bl[nt]);
                    mma_bf16(acc[mt][nt], al, bh[nt]);
                }
            }
        }
        __syncthreads();
    }

    #pragma unroll
    for (int mt = 0; mt < 4; mt++) {
        int rbase = bm + wm + mt*16 + (lane >> 2);
        #pragma unroll
        for (int half = 0; half < 2; half++) {
            int rr = rbase + half*8;
            if (rr < M) {
                #pragma unroll
                for (int nt = 0; nt < 4; nt++) {
                    int cc = bn + wn + nt*8 + 2*(lane & 3);
                    float v0 = alpha*acc[mt][nt][half*2 + 0];
                    float v1 = alpha*acc[mt][nt][half*2 + 1];
                    *(float2*)(C + (size_t)rr*N + cc) = make_float2(v0, v1);
                }
            }
        }
    }
}

// readout: node_out = h @ Wout, segment-sum by graph
__global__ void readout_kernel(const float* __restrict__ h,
                               const float* __restrict__ Wout,
                               const int* __restrict__ batch) {
    int n = blockIdx.x*8 + (threadIdx.x >> 5);
    int lane = threadIdx.x & 31;
    if (n >= N_NODES) return;
    float s = 0.0f;
    #pragma unroll
    for (int k = 0; k < 8; k++)
        s += h[(size_t)n*HDIM + k*32 + lane]*Wout[k*32 + lane];
    #pragma unroll
    for (int o = 16; o > 0; o >>= 1) s += __shfl_xor_sync(0xffffffffu, s, o);
    if (lane == 0) atomicAdd(&g_sums[batch[n]], s);
}

__global__ void finalize_kernel(float* __restrict__ out) {
    int g = threadIdx.x;
    if (g < N_GRAPHS) out[g] = g_sums[g]/fmaxf(g_cnts[g], 1.0f);
}

// ---------------- launch ----------------
extern "C" void kernel_launch(void* const* d_in, const int* in_sizes, int n_in,
                              void* d_out, int out_size) {
    (void)in_sizes; (void)n_in; (void)out_size;
    const float* x       = (const float*)d_in[0];
    const float* pos     = (const float*)d_in[1];
    const float* shift   = (const float*)d_in[2];
    const float* lattice = (const float*)d_in[3];
    const float* W_embed = (const float*)d_in[4];
    const float* r1      = (const float*)d_in[5];
    const float* b1      = (const float*)d_in[6];
    const float* r2      = (const float*)d_in[7];
    const float* Wtp     = (const float*)d_in[8];
    const float* Wself   = (const float*)d_in[9];
    const float* Wskip   = (const float*)d_in[10];
    const float* Wout    = (const float*)d_in[11];
    const int*   eidx    = (const int*)d_in[12];
    const int*   batch   = (const int*)d_in[13];
    const int* esrc = eidx;
    const int* edst = eidx + N_EDGES;
    float* out = (float*)d_out;

    float *hA, *hB, *wtp2;
    __nv_bfloat16 *bhi, *blo;
    __half *w16h, *w16l, *Gh, *Gl;
    cudaGetSymbolAddress((void**)&hA,   g_hA);
    cudaGetSymbolAddress((void**)&hB,   g_hB);
    cudaGetSymbolAddress((void**)&wtp2, g_wtp2);
    cudaGetSymbolAddress((void**)&bhi,  g_bhi);
    cudaGetSymbolAddress((void**)&blo,  g_blo);
    cudaGetSymbolAddress((void**)&w16h, g_w16h);
    cudaGetSymbolAddress((void**)&w16l, g_w16l);
    cudaGetSymbolAddress((void**)&Gh,   g_G16h);
    cudaGetSymbolAddress((void**)&Gl,   g_G16l);

    cudaFuncSetAttribute(mma_gemm_node, cudaFuncAttributeMaxDynamicSharedMemorySize, 3*SSTGN);

    const int TB = 256;
    zero_kernel<<<(N_NODES + TB - 1)/TB, TB>>>();
    hist_kernel<<<(N_EDGES + TB - 1)/TB, TB>>>(edst, batch);
    scan_kernel<<<1, 1024>>>();
    build_csr_kernel<<<(N_EDGES + TB - 1)/TB, TB>>>(edst);
    edge_geom_kernel<<<(N_EDGES + TB - 1)/TB, TB>>>(pos, shift, lattice, batch, esrc, edst);

    const float inv_sqrt_deg = 0.28867513459481287f;  // 1/sqrt(12)

    // embed weights: bf16 hi/lo (accuracy path)
    convertB_kernel<<<(HDIM*128 + TB - 1)/TB, TB>>>(W_embed, bhi + OFF_EMB, blo + OFF_EMB,
                                                    D_IN, 128, 128, 0, HDIM);
    for (int l = 0; l < NLAYER; l++) {
        // Wcomb[l] = [ inv_sqrt_deg * Wtp@Wself | Wskip ] -> fp16 hi/lo [256][2560]
        convertB_kernel<<<(HDIM*256 + TB - 1)/TB, TB>>>(Wself + (size_t)l*HDIM*HDIM,
            bhi + OFF_WSELFT, blo + OFF_WSELFT, HDIM, 256, 256, 0, HDIM);
        dim3 gComb(2, KTP/128);
        mma_gemm<<<gComb, 256>>>(KTP, HDIM, 256, Wtp + (size_t)l*KTP*HDIM,
                                 bhi + OFF_WSELFT, blo + OFF_WSELFT,
                                 wtp2 + (size_t)l*KTP*HDIM, inv_sqrt_deg);
        convertW16s_kernel<<<(HDIM*KTP + TB - 1)/TB, TB>>>(wtp2 + (size_t)l*KTP*HDIM,
            w16h + (size_t)l*HDIM*KPAD2, w16l + (size_t)l*HDIM*KPAD2,
            KTP, KTP, KPAD2, 0, HDIM);
        convertW16s_kernel<<<(HDIM*256 + TB - 1)/TB, TB>>>(Wskip + (size_t)l*HDIM*HDIM,
            w16h + (size_t)l*HDIM*KPAD2, w16l + (size_t)l*HDIM*KPAD2,
            HDIM, 256, KPAD2, KTP, HDIM);
    }

    // h = x @ W_embed  (fp32-A bf16-split path for accuracy)
    dim3 gEmbed(2, (N_NODES + 127)/128);
    mma_gemm<<<gEmbed, 256>>>(N_NODES, D_IN, 128, x, bhi + OFF_EMB, blo + OFF_EMB, hA, 1.0f);
    storeH16_kernel<<<(N_NODES*HDIM + TB - 1)/TB, TB>>>(hA);

    dim3 gNode(2, (N_NODES + 63)/64);   // (2, 313)
    int gTab = (NBINS + 1 + 7)/8;       // 529

    float* hc = hA;
    float* hn = hB;

    for (int l = 0; l < NLAYER; l++) {
        // build radial lookup table for this layer (replaces act kernel + radial GEMM)
        rtab_kernel<<<gTab, 256>>>(r1 + l*NB*RH, b1 + l*RH, r2 + (size_t)l*RH*HDIM);
        scatter_kernel<<<(N_NODES + 7)/8, 256>>>(hc, esrc);
        // hn = gelu( G @ Wtp' + h @ Wskip ): 2-term fp16 + exact 3rd term on h tail
        mma_gemm_node<<<gNode, 256, 3*SSTGN>>>(N_NODES, KPAD2, KTP, Gh, Gl,
            w16h + (size_t)l*HDIM*KPAD2, w16l + (size_t)l*HDIM*KPAD2, hn);
        if (l + 1 < NLAYER)
            storeH16_kernel<<<(N_NODES*HDIM + TB - 1)/TB, TB>>>(hn);
        float* t = hc; hc = hn; hn = t;
    }

    readout_kernel<<<(N_NODES + 7)/8, 256>>>(hc, Wout, batch);
    finalize_kernel<<<1, 256>>>(out);
}